// round 10
// baseline (speedup 1.0000x reference)
#include <cuda_runtime.h>
#include <cuda_bf16.h>
#include <cstdint>

// Problem constants
#define BB    2048     // batch
#define HB    1024     // half batch
#define KHIST 200      // history length
#define DD    512      // latent dim
#define HHID  1024     // 2*D
#define CBK   2048     // codebook size
#define BD    (BB*DD)  // 1048576
#define NBW   64       // CBK / 32 argmin partial chunks per row
#define GBLK  296      // gather grid (2 CTAs/SM) — co-residency with GEMM CTAs

// ---------------- scratch (device globals; no allocation allowed) ----------
__device__ float        g_u[BB * DD];
__device__ float        g_cnorm[CBK];
__device__ float        g_pval[BB * NBW];
__device__ int          g_pidx[BB * NBW];
__device__ float        g_bsum[BB];
__device__ int          g_count;          // zero-init; self-resetting

// bf16 hi/lo split operands
__device__ __nv_bfloat16 g_meanH[BB * DD],   g_meanL[BB * DD];
__device__ __nv_bfloat16 g_hidH [BB * HHID], g_hidL [BB * HHID];
__device__ __nv_bfloat16 g_uH   [BB * DD],   g_uL   [BB * DD];
__device__ __nv_bfloat16 g_W1tH [HHID * DD], g_W1tL [HHID * DD];
__device__ __nv_bfloat16 g_W2tH [DD * HHID], g_W2tL [DD * HHID];
__device__ __nv_bfloat16 g_cbH  [CBK * DD],  g_cbL  [CBK * DD];

// ---------------------------------------------------------------------------
// Portable PTX helpers
// ---------------------------------------------------------------------------
__device__ __forceinline__ uint32_t smem_u32(const void* p) {
    uint32_t a;
    asm("{ .reg .u64 t; cvta.to.shared.u64 t, %1; cvt.u32.u64 %0, t; }" : "=r"(a) : "l"(p));
    return a;
}

#define CP_ASYNC16(dst, src) \
    asm volatile("cp.async.cg.shared.global [%0], [%1], 16;" :: "r"(dst), "l"(src))
#define CP_COMMIT() asm volatile("cp.async.commit_group;" ::: "memory")
#define CP_WAIT0()  asm volatile("cp.async.wait_group 0;" ::: "memory")
#define CP_WAIT1()  asm volatile("cp.async.wait_group 1;" ::: "memory")

__device__ __forceinline__ void ldsm4(uint32_t (&r)[4], uint32_t addr) {
    asm volatile("ldmatrix.sync.aligned.m8n8.x4.shared.b16 {%0,%1,%2,%3}, [%4];"
                 : "=r"(r[0]), "=r"(r[1]), "=r"(r[2]), "=r"(r[3]) : "r"(addr));
}

__device__ __forceinline__ void mma16816(float (&d)[4], const uint32_t (&a)[4],
                                         uint32_t b0, uint32_t b1) {
    asm volatile(
        "mma.sync.aligned.m16n8k16.row.col.f32.bf16.bf16.f32 "
        "{%0,%1,%2,%3}, {%4,%5,%6,%7}, {%8,%9}, {%0,%1,%2,%3};"
        : "+f"(d[0]), "+f"(d[1]), "+f"(d[2]), "+f"(d[3])
        : "r"(a[0]), "r"(a[1]), "r"(a[2]), "r"(a[3]), "r"(b0), "r"(b1));
}

__device__ __forceinline__ void split_bf16(float v, __nv_bfloat16& h, __nv_bfloat16& l) {
    h = __float2bfloat16(v);
    l = __float2bfloat16(v - __bfloat162float(h));
}

// ---------------------------------------------------------------------------
// Gather+mean for one half, residency-bounded: GBLK CTAs x 256 threads,
// 2 rows per block-iteration, grid-strided. Low reg/smem footprint so GEMM
// CTAs can co-reside on the same SMs (register file is the binding resource).
// ---------------------------------------------------------------------------
__global__ void __launch_bounds__(256) gather_kernel(
    const int* __restrict__ items, const float* __restrict__ item_embed, int row0)
{
    __shared__ int sidx[2][KHIST];
    const int t = threadIdx.x;
    const int half = t >> 7, tt = t & 127;
    const float4* E4 = (const float4*)item_embed;

    #pragma unroll
    for (int it = 0; it < 2; it++) {
        int bl = it * (2 * GBLK) + blockIdx.x * 2 + half;
        bool active = (bl < HB);
        int b = row0 + (active ? bl : 0);

        __syncthreads();    // protect sidx reuse across iterations
        if (active)
            for (int i = tt; i < KHIST; i += 128) sidx[half][i] = items[b * KHIST + i];
        __syncthreads();
        if (!active) continue;

        float4 acc = make_float4(0.f, 0.f, 0.f, 0.f);
        int cnt = 0;
        #pragma unroll 8
        for (int k = 0; k < KHIST; k++) {
            int idx = sidx[half][k];
            float m = (idx != 0) ? 1.0f : 0.0f;
            cnt += (idx != 0);
            float4 v = E4[(size_t)idx * 128 + tt];
            acc.x += m * v.x; acc.y += m * v.y; acc.z += m * v.z; acc.w += m * v.w;
        }
        float inv = 1.0f / (float)cnt;
        float vals[4] = {acc.x * inv, acc.y * inv, acc.z * inv, acc.w * inv};
        size_t base = (size_t)b * DD + tt * 4;
        __nv_bfloat16 h[4], l[4];
        #pragma unroll
        for (int i = 0; i < 4; i++) split_bf16(vals[i], h[i], l[i]);
        *(__nv_bfloat162*)&g_meanH[base]     = {h[0], h[1]};
        *(__nv_bfloat162*)&g_meanH[base + 2] = {h[2], h[3]};
        *(__nv_bfloat162*)&g_meanL[base]     = {l[0], l[1]};
        *(__nv_bfloat162*)&g_meanL[base + 2] = {l[2], l[3]};
    }
}

// ---------------------------------------------------------------------------
// Misc prep: codebook split+norms (2048) | W1t split (512) | W2t split (512)
// ---------------------------------------------------------------------------
__global__ void __launch_bounds__(128) misc_prep_kernel(
    const float* __restrict__ codebook,
    const float* __restrict__ W1, const float* __restrict__ W2)
{
    __shared__ float ts[32][33];
    __shared__ float red[4];
    const int blk = blockIdx.x;
    const int t = threadIdx.x;

    if (blk < 2048) {
        int j = blk;
        float4 v = ((const float4*)codebook)[j * 128 + t];
        float vals[4] = {v.x, v.y, v.z, v.w};
        size_t base = (size_t)j * DD + t * 4;
        __nv_bfloat16 h[4], l[4];
        #pragma unroll
        for (int i = 0; i < 4; i++) split_bf16(vals[i], h[i], l[i]);
        *(__nv_bfloat162*)&g_cbH[base]     = {h[0], h[1]};
        *(__nv_bfloat162*)&g_cbH[base + 2] = {h[2], h[3]};
        *(__nv_bfloat162*)&g_cbL[base]     = {l[0], l[1]};
        *(__nv_bfloat162*)&g_cbL[base + 2] = {l[2], l[3]};

        float s = v.x * v.x + v.y * v.y + v.z * v.z + v.w * v.w;
        #pragma unroll
        for (int o = 16; o > 0; o >>= 1) s += __shfl_down_sync(0xffffffffu, s, o);
        if ((t & 31) == 0) red[t >> 5] = s;
        __syncthreads();
        if (t == 0) g_cnorm[j] = red[0] + red[1] + red[2] + red[3];
    } else {
        const float* W;
        __nv_bfloat16 *WtH, *WtL;
        int KD, ND, w;
        if (blk < 2560) {
            w = blk - 2048; W = W1; WtH = g_W1tH; WtL = g_W1tL; KD = DD; ND = HHID;
        } else {
            w = blk - 2560; W = W2; WtH = g_W2tH; WtL = g_W2tL; KD = HHID; ND = DD;
        }
        int nblk = ND / 32;
        int n0 = (w % nblk) * 32, k0 = (w / nblk) * 32;
        int tx = t & 31, ty = t >> 5;
        #pragma unroll
        for (int i = ty; i < 32; i += 4)
            ts[i][tx] = W[(size_t)(k0 + i) * ND + n0 + tx];
        __syncthreads();
        #pragma unroll
        for (int i = ty; i < 32; i += 4) {
            float v = ts[tx][i];
            __nv_bfloat16 h, l;
            split_bf16(v, h, l);
            size_t o = (size_t)(n0 + i) * KD + k0 + tx;
            WtH[o] = h;
            WtL[o] = l;
        }
    }
}

// ---------------------------------------------------------------------------
// Tensor-core GEMM (mma.sync bf16x3, fp32 accum): C = A[M,Kd] @ B[N,Kd]^T
// Identical math to R7; row0 selects the batch half.
// ---------------------------------------------------------------------------
template<int BM, int WHICH>
__global__ void __launch_bounds__(256, (BM == 64) ? 3 : 2) gemm_mma(
    const __nv_bfloat16* __restrict__ Ah, const __nv_bfloat16* __restrict__ Al,
    const __nv_bfloat16* __restrict__ Bh, const __nv_bfloat16* __restrict__ Bl,
    const float* __restrict__ bias, float* __restrict__ out_ue,
    int N, int Kd, int row0)
{
    constexpr int BN  = 64;
    constexpr int WM  = BM / 4;
    constexpr int MT  = WM / 16;
    constexpr int STAGE = 2 * (BM + BN) * 128;

    extern __shared__ char smem[];
    const uint32_t sbase = smem_u32(smem);
    const int tid  = threadIdx.x;
    const int lane = tid & 31;
    const int w    = tid >> 5;
    const int warp_m0 = (w >> 1) * WM;
    const int warp_n0 = (w & 1) * 32;
    const int bm = row0 + blockIdx.y * BM, bn = blockIdx.x * BN;

    auto loadT = [&](const __nv_bfloat16* __restrict__ src, int r0, int k0,
                     uint32_t dst, int R) {
        #pragma unroll 4
        for (int i = 0; i < R * 8; i += 256) {
            int u = tid + i;
            int r = u >> 3, c8 = u & 7;
            uint32_t sd = dst + r * 128 + ((c8 * 16) ^ ((r & 7) << 4));
            const __nv_bfloat16* gs = src + (size_t)(r0 + r) * Kd + k0 + c8 * 8;
            CP_ASYNC16(sd, gs);
        }
    };
    auto issue = [&](int c, int buf) {
        uint32_t sb = sbase + (uint32_t)buf * STAGE;
        int k0 = c * 64;
        loadT(Ah, bm, k0, sb, BM);
        loadT(Al, bm, k0, sb + BM * 128, BM);
        loadT(Bh, bn, k0, sb + 2 * BM * 128, BN);
        loadT(Bl, bn, k0, sb + 2 * BM * 128 + BN * 128, BN);
    };

    const int tile = lane >> 3, lr = lane & 7;
    const uint32_t xorp = (uint32_t)(lr << 4);
    const int aRow = warp_m0 + ((tile & 1) << 3) + lr;
    const uint32_t aK = (uint32_t)((tile >> 1) << 4);
    const int bRow = warp_n0 + ((tile >> 1) << 3) + lr;
    const uint32_t bK = (uint32_t)((tile & 1) << 4);

    float acc[MT][4][4] = {};

    const int NC = Kd / 64;
    issue(0, 0); CP_COMMIT();
    issue(1, 1); CP_COMMIT();
    CP_WAIT1();
    __syncthreads();

    for (int c = 0; c < NC; c++) {
        uint32_t s0 = sbase + (uint32_t)(c & 1) * STAGE;
        uint32_t pA[2] = { s0, s0 + BM * 128 };
        uint32_t pB[2] = { s0 + 2 * BM * 128, s0 + 2 * BM * 128 + BN * 128 };

        #pragma unroll
        for (int kk = 0; kk < 4; kk++) {
            uint32_t akb = (((uint32_t)kk << 5) + aK) ^ xorp;
            uint32_t bkb = (((uint32_t)kk << 5) + bK) ^ xorp;
            uint32_t a[2][MT][4];
            uint32_t b[2][4][2];
            #pragma unroll
            for (int s = 0; s < 2; s++)
                #pragma unroll
                for (int mt = 0; mt < MT; mt++)
                    ldsm4(a[s][mt], pA[s] + (uint32_t)(aRow + mt * 16) * 128 + akb);
            #pragma unroll
            for (int s = 0; s < 2; s++)
                #pragma unroll
                for (int ng = 0; ng < 2; ng++) {
                    uint32_t t4[4];
                    ldsm4(t4, pB[s] + (uint32_t)(bRow + ng * 16) * 128 + bkb);
                    b[s][2 * ng][0] = t4[0]; b[s][2 * ng][1] = t4[1];
                    b[s][2 * ng + 1][0] = t4[2]; b[s][2 * ng + 1][1] = t4[3];
                }
            #pragma unroll
            for (int mt = 0; mt < MT; mt++)
                #pragma unroll
                for (int nt = 0; nt < 4; nt++)
                    mma16816(acc[mt][nt], a[0][mt], b[0][nt][0], b[0][nt][1]);
            #pragma unroll
            for (int mt = 0; mt < MT; mt++)
                #pragma unroll
                for (int nt = 0; nt < 4; nt++)
                    mma16816(acc[mt][nt], a[0][mt], b[1][nt][0], b[1][nt][1]);
            #pragma unroll
            for (int mt = 0; mt < MT; mt++)
                #pragma unroll
                for (int nt = 0; nt < 4; nt++)
                    mma16816(acc[mt][nt], a[1][mt], b[0][nt][0], b[0][nt][1]);
        }

        if (c == NC - 1) break;
        __syncthreads();
        if (c + 2 < NC) { issue(c + 2, c & 1); CP_COMMIT(); CP_WAIT1(); }
        else            { CP_WAIT0(); }
        __syncthreads();
    }

    const int lr4 = lane >> 2;
    const int lc2 = (lane & 3) * 2;

    if (WHICH == 2) {
        int chunk = (bn + warp_n0) >> 5;
        #pragma unroll
        for (int mt = 0; mt < MT; mt++)
            #pragma unroll
            for (int half = 0; half < 2; half++) {
                int row = bm + warp_m0 + mt * 16 + lr4 + half * 8;
                float mv = 3.0e38f; int mj = 0x7fffffff;
                #pragma unroll
                for (int nt = 0; nt < 4; nt++) {
                    int col = bn + warp_n0 + nt * 8 + lc2;
                    float2 cn = *(const float2*)&g_cnorm[col];
                    float s0 = cn.x - 2.0f * acc[mt][nt][half * 2 + 0];
                    float s1 = cn.y - 2.0f * acc[mt][nt][half * 2 + 1];
                    if (s0 < mv) { mv = s0; mj = col; }
                    if (s1 < mv) { mv = s1; mj = col + 1; }
                }
                #pragma unroll
                for (int o = 1; o < 4; o <<= 1) {
                    float ov = __shfl_xor_sync(0xffffffffu, mv, o);
                    int   oj = __shfl_xor_sync(0xffffffffu, mj, o);
                    if (ov < mv || (ov == mv && oj < mj)) { mv = ov; mj = oj; }
                }
                if ((lane & 3) == 0) {
                    g_pval[(size_t)row * NBW + chunk] = mv;
                    g_pidx[(size_t)row * NBW + chunk] = mj;
                }
            }
    } else {
        #pragma unroll
        for (int mt = 0; mt < MT; mt++)
            #pragma unroll
            for (int half = 0; half < 2; half++) {
                int row = bm + warp_m0 + mt * 16 + lr4 + half * 8;
                #pragma unroll
                for (int nt = 0; nt < 4; nt++) {
                    int col = bn + warp_n0 + nt * 8 + lc2;
                    float2 bv = *(const float2*)&bias[col];
                    float v0 = acc[mt][nt][half * 2 + 0] + bv.x;
                    float v1 = acc[mt][nt][half * 2 + 1] + bv.y;
                    size_t o = (size_t)row * N + col;
                    if (WHICH == 0) {
                        v0 = fmaxf(v0, 0.f); v1 = fmaxf(v1, 0.f);
                        __nv_bfloat16 h0, l0, h1, l1;
                        split_bf16(v0, h0, l0); split_bf16(v1, h1, l1);
                        *(__nv_bfloat162*)&g_hidH[o] = {h0, h1};
                        *(__nv_bfloat162*)&g_hidL[o] = {l0, l1};
                    } else {
                        *(float2*)&g_u[o] = make_float2(v0, v1);
                        out_ue[o] = v0; out_ue[o + 1] = v1;
                        __nv_bfloat16 h0, l0, h1, l1;
                        split_bf16(v0, h0, l0); split_bf16(v1, h1, l1);
                        *(__nv_bfloat162*)&g_uH[o] = {h0, h1};
                        *(__nv_bfloat162*)&g_uL[o] = {l0, l1};
                    }
                }
            }
    }
}

// ---------------------------------------------------------------------------
// Epilogue for one half (grid = HB): final argmin over 64 partials, VQ
// outputs, pos/neg gathers, diff partials; last block overall does the
// fixed-tree diff reduction and resets the counter for graph replay.
// ---------------------------------------------------------------------------
__global__ void __launch_bounds__(128) epilogue_kernel(
    const float* __restrict__ codebook, const float* __restrict__ item_embed,
    const int* __restrict__ pos, const int* __restrict__ neg,
    float* __restrict__ out_q, float* __restrict__ out_pos,
    float* __restrict__ out_neg, float* __restrict__ out_diff, int row0)
{
    int b = row0 + blockIdx.x;
    int t = threadIdx.x;

    __shared__ float pv[64];
    __shared__ int   pi[64];
    __shared__ int   s_id;
    __shared__ bool  s_last;
    if (t < 64) {
        pv[t] = g_pval[(size_t)b * NBW + t];
        pi[t] = g_pidx[(size_t)b * NBW + t];
    }
    __syncthreads();
    if (t < 32) {
        float v1 = pv[t]; int i1 = pi[t];
        float v2 = pv[t + 32]; int i2 = pi[t + 32];
        if (v2 < v1 || (v2 == v1 && i2 < i1)) { v1 = v2; i1 = i2; }
        #pragma unroll
        for (int o = 16; o > 0; o >>= 1) {
            float ov = __shfl_down_sync(0xffffffffu, v1, o);
            int   oi = __shfl_down_sync(0xffffffffu, i1, o);
            if (ov < v1 || (ov == v1 && oi < i1)) { v1 = ov; i1 = oi; }
        }
        if (t == 0) s_id = i1;
    }
    __syncthreads();
    int id = s_id;

    float4 q = ((const float4*)codebook)[(size_t)id * 128 + t];
    float4 u = ((const float4*)g_u)[(size_t)b * 128 + t];
    float4 d = make_float4(q.x - u.x, q.y - u.y, q.z - u.z, q.w - u.w);
    float4 qu = make_float4(u.x + d.x, u.y + d.y, u.z + d.z, u.w + d.w);
    ((float4*)out_q)[(size_t)b * 128 + t] = qu;

    int p = pos[b], n = neg[b];
    ((float4*)out_pos)[(size_t)b * 128 + t] = ((const float4*)item_embed)[(size_t)p * 128 + t];
    ((float4*)out_neg)[(size_t)b * 128 + t] = ((const float4*)item_embed)[(size_t)n * 128 + t];

    float ds = d.x * d.x + d.y * d.y + d.z * d.z + d.w * d.w;
    #pragma unroll
    for (int o = 16; o > 0; o >>= 1) ds += __shfl_down_sync(0xffffffffu, ds, o);
    __shared__ float red[4];
    if ((t & 31) == 0) red[t >> 5] = ds;
    __syncthreads();
    if (t == 0) {
        g_bsum[b] = red[0] + red[1] + red[2] + red[3];
        __threadfence();
        int c = atomicAdd(&g_count, 1);
        s_last = (c == BB - 1);
    }
    __syncthreads();

    if (s_last) {
        __threadfence();
        float s = 0.f;
        #pragma unroll
        for (int i = 0; i < BB / 128; i++) s += g_bsum[t + i * 128];
        __shared__ float sv[128];
        sv[t] = s;
        __syncthreads();
        for (int o = 64; o > 0; o >>= 1) {
            if (t < o) sv[t] += sv[t + o];
            __syncthreads();
        }
        if (t == 0) {
            *out_diff = sv[0] * (1.0f / (float)BD);
            g_count = 0;                       // reset for next graph replay
        }
    }
}

// ---------------------------------------------------------------------------
extern "C" void kernel_launch(void* const* d_in, const int* in_sizes, int n_in,
                              void* d_out, int out_size)
{
    const int*   items      = (const int*)  d_in[1];
    const int*   pos        = (const int*)  d_in[2];
    const int*   neg        = (const int*)  d_in[3];
    const float* item_embed = (const float*)d_in[4];
    const float* W1         = (const float*)d_in[5];
    const float* b1         = (const float*)d_in[6];
    const float* W2         = (const float*)d_in[7];
    const float* b2         = (const float*)d_in[8];
    const float* codebook   = (const float*)d_in[9];

    float* out      = (float*)d_out;
    float* out_q    = out;
    float* out_pos  = out + (size_t)BD;
    float* out_neg  = out + (size_t)2 * BD;
    float* out_diff = out + (size_t)3 * BD;
    float* out_ue   = out + (size_t)3 * BD + 1;

    const int SMEM_128 = 2 * 2 * (128 + 64) * 128;  // 98304
    const int SMEM_64  = 2 * 2 * (64 + 64) * 128;   // 65536

    // One-time setup on the first (uncaptured, correctness) call.
    static cudaStream_t s1 = nullptr;
    static cudaEvent_t evFork = nullptr, evMisc = nullptr, evG0 = nullptr, evEnd1 = nullptr;
    if (s1 == nullptr) {
        cudaFuncSetAttribute((const void*)gemm_mma<128, 0>,
                             cudaFuncAttributeMaxDynamicSharedMemorySize, SMEM_128);
        cudaFuncSetAttribute((const void*)gemm_mma<64, 1>,
                             cudaFuncAttributeMaxDynamicSharedMemorySize, SMEM_64);
        cudaFuncSetAttribute((const void*)gemm_mma<128, 2>,
                             cudaFuncAttributeMaxDynamicSharedMemorySize, SMEM_128);
        cudaStreamCreateWithFlags(&s1, cudaStreamNonBlocking);
        cudaEventCreateWithFlags(&evFork, cudaEventDisableTiming);
        cudaEventCreateWithFlags(&evMisc, cudaEventDisableTiming);
        cudaEventCreateWithFlags(&evG0,   cudaEventDisableTiming);
        cudaEventCreateWithFlags(&evEnd1, cudaEventDisableTiming);
    }

    __nv_bfloat16 *meanH, *meanL, *hidH, *hidL, *uH, *uL, *w1tH, *w1tL, *w2tH, *w2tL, *cbH, *cbL;
    cudaGetSymbolAddress((void**)&meanH, g_meanH);
    cudaGetSymbolAddress((void**)&meanL, g_meanL);
    cudaGetSymbolAddress((void**)&hidH,  g_hidH);
    cudaGetSymbolAddress((void**)&hidL,  g_hidL);
    cudaGetSymbolAddress((void**)&uH,    g_uH);
    cudaGetSymbolAddress((void**)&uL,    g_uL);
    cudaGetSymbolAddress((void**)&w1tH,  g_W1tH);
    cudaGetSymbolAddress((void**)&w1tL,  g_W1tL);
    cudaGetSymbolAddress((void**)&w2tH,  g_W2tH);
    cudaGetSymbolAddress((void**)&w2tL,  g_W2tL);
    cudaGetSymbolAddress((void**)&cbH,   g_cbH);
    cudaGetSymbolAddress((void**)&cbL,   g_cbL);

    // ---- fork: s1 runs misc prep concurrently with gather(h0) on stream 0 ----
    cudaEventRecord(evFork, 0);
    cudaStreamWaitEvent(s1, evFork, 0);
    misc_prep_kernel<<<3072, 128, 0, s1>>>(codebook, W1, W2);
    cudaEventRecord(evMisc, s1);

    gather_kernel<<<GBLK, 256>>>(items, item_embed, 0);      // stream 0: half 0
    cudaEventRecord(evG0, 0);
    cudaStreamWaitEvent(s1, evG0, 0);

    // ---- s1: half-0 GEMM chain + epilogue (co-resident with gather(h1)) ----
    gemm_mma<128, 0><<<dim3(HHID / 64, HB / 128), 256, SMEM_128, s1>>>(
        meanH, meanL, w1tH, w1tL, b1, nullptr, HHID, DD, 0);
    gemm_mma<64, 1><<<dim3(DD / 64, HB / 64), 256, SMEM_64, s1>>>(
        hidH,  hidL,  w2tH, w2tL, b2, out_ue,  DD,  HHID, 0);
    gemm_mma<128, 2><<<dim3(CBK / 64, HB / 128), 256, SMEM_128, s1>>>(
        uH,    uL,    cbH,  cbL,  nullptr, nullptr, CBK, DD, 0);
    epilogue_kernel<<<HB, 128, 0, s1>>>(codebook, item_embed, pos, neg,
                                        out_q, out_pos, out_neg, out_diff, 0);
    cudaEventRecord(evEnd1, s1);

    // ---- stream 0: gather(h1) co-runs with the h0 chain; then h1 chain ----
    gather_kernel<<<GBLK, 256>>>(items, item_embed, HB);
    cudaStreamWaitEvent(0, evMisc, 0);   // W/cb splits ready before gemm0(h1)
    gemm_mma<128, 0><<<dim3(HHID / 64, HB / 128), 256, SMEM_128>>>(
        meanH, meanL, w1tH, w1tL, b1, nullptr, HHID, DD, HB);
    gemm_mma<64, 1><<<dim3(DD / 64, HB / 64), 256, SMEM_64>>>(
        hidH,  hidL,  w2tH, w2tL, b2, out_ue,  DD,  HHID, HB);
    gemm_mma<128, 2><<<dim3(CBK / 64, HB / 128), 256, SMEM_128>>>(
        uH,    uL,    cbH,  cbL,  nullptr, nullptr, CBK, DD, HB);
    epilogue_kernel<<<HB, 128>>>(codebook, item_embed, pos, neg,
                                 out_q, out_pos, out_neg, out_diff, HB);

    // ---- join s1 back into stream 0 ----
    cudaStreamWaitEvent(0, evEnd1, 0);
}

// round 11
// speedup vs baseline: 1.0001x; 1.0001x over previous
#include <cuda_runtime.h>
#include <cuda_bf16.h>
#include <cstdint>

// Problem constants
#define BB    2048     // batch
#define HB    1024     // half batch
#define KHIST 200      // history length
#define DD    512      // latent dim
#define HHID  1024     // 2*D
#define CBK   2048     // codebook size
#define BD    (BB*DD)  // 1048576
#define NBW   64       // CBK / 32 argmin partial chunks per row
#define GBLK  296      // gather grid (2 CTAs/SM) — co-residency with GEMM CTAs

// ---------------- scratch (device globals; no allocation allowed) ----------
__device__ float        g_u[BB * DD];
__device__ float        g_cnorm[CBK];
__device__ float        g_pval[BB * NBW];
__device__ int          g_pidx[BB * NBW];
__device__ float        g_bsum[BB];
__device__ int          g_count;          // zero-init; self-resetting

// bf16 hi/lo split operands
__device__ __nv_bfloat16 g_meanH[BB * DD],   g_meanL[BB * DD];
__device__ __nv_bfloat16 g_hidH [BB * HHID], g_hidL [BB * HHID];
__device__ __nv_bfloat16 g_uH   [BB * DD],   g_uL   [BB * DD];
__device__ __nv_bfloat16 g_W1tH [HHID * DD], g_W1tL [HHID * DD];
__device__ __nv_bfloat16 g_W2tH [DD * HHID], g_W2tL [DD * HHID];
__device__ __nv_bfloat16 g_cbH  [CBK * DD],  g_cbL  [CBK * DD];

// ---------------------------------------------------------------------------
// Portable PTX helpers
// ---------------------------------------------------------------------------
__device__ __forceinline__ uint32_t smem_u32(const void* p) {
    uint32_t a;
    asm("{ .reg .u64 t; cvta.to.shared.u64 t, %1; cvt.u32.u64 %0, t; }" : "=r"(a) : "l"(p));
    return a;
}

#define CP_ASYNC16(dst, src) \
    asm volatile("cp.async.cg.shared.global [%0], [%1], 16;" :: "r"(dst), "l"(src))
#define CP_COMMIT() asm volatile("cp.async.commit_group;" ::: "memory")
#define CP_WAIT0()  asm volatile("cp.async.wait_group 0;" ::: "memory")
#define CP_WAIT1()  asm volatile("cp.async.wait_group 1;" ::: "memory")

__device__ __forceinline__ void ldsm4(uint32_t (&r)[4], uint32_t addr) {
    asm volatile("ldmatrix.sync.aligned.m8n8.x4.shared.b16 {%0,%1,%2,%3}, [%4];"
                 : "=r"(r[0]), "=r"(r[1]), "=r"(r[2]), "=r"(r[3]) : "r"(addr));
}

__device__ __forceinline__ void mma16816(float (&d)[4], const uint32_t (&a)[4],
                                         uint32_t b0, uint32_t b1) {
    asm volatile(
        "mma.sync.aligned.m16n8k16.row.col.f32.bf16.bf16.f32 "
        "{%0,%1,%2,%3}, {%4,%5,%6,%7}, {%8,%9}, {%0,%1,%2,%3};"
        : "+f"(d[0]), "+f"(d[1]), "+f"(d[2]), "+f"(d[3])
        : "r"(a[0]), "r"(a[1]), "r"(a[2]), "r"(a[3]), "r"(b0), "r"(b1));
}

__device__ __forceinline__ void split_bf16(float v, __nv_bfloat16& h, __nv_bfloat16& l) {
    h = __float2bfloat16(v);
    l = __float2bfloat16(v - __bfloat162float(h));
}

// ---------------------------------------------------------------------------
// Gather+mean for one half, residency-bounded: GBLK CTAs x 256 threads,
// 2 rows per block-iteration, grid-strided. Low reg/smem footprint so GEMM
// CTAs can co-reside on the same SMs (register file is the binding resource).
// ---------------------------------------------------------------------------
__global__ void __launch_bounds__(256) gather_kernel(
    const int* __restrict__ items, const float* __restrict__ item_embed, int row0)
{
    __shared__ int sidx[2][KHIST];
    const int t = threadIdx.x;
    const int half = t >> 7, tt = t & 127;
    const float4* E4 = (const float4*)item_embed;

    #pragma unroll
    for (int it = 0; it < 2; it++) {
        int bl = it * (2 * GBLK) + blockIdx.x * 2 + half;
        bool active = (bl < HB);
        int b = row0 + (active ? bl : 0);

        __syncthreads();    // protect sidx reuse across iterations
        if (active)
            for (int i = tt; i < KHIST; i += 128) sidx[half][i] = items[b * KHIST + i];
        __syncthreads();
        if (!active) continue;

        float4 acc = make_float4(0.f, 0.f, 0.f, 0.f);
        int cnt = 0;
        #pragma unroll 8
        for (int k = 0; k < KHIST; k++) {
            int idx = sidx[half][k];
            float m = (idx != 0) ? 1.0f : 0.0f;
            cnt += (idx != 0);
            float4 v = E4[(size_t)idx * 128 + tt];
            acc.x += m * v.x; acc.y += m * v.y; acc.z += m * v.z; acc.w += m * v.w;
        }
        float inv = 1.0f / (float)cnt;
        float vals[4] = {acc.x * inv, acc.y * inv, acc.z * inv, acc.w * inv};
        size_t base = (size_t)b * DD + tt * 4;
        __nv_bfloat16 h[4], l[4];
        #pragma unroll
        for (int i = 0; i < 4; i++) split_bf16(vals[i], h[i], l[i]);
        *(__nv_bfloat162*)&g_meanH[base]     = {h[0], h[1]};
        *(__nv_bfloat162*)&g_meanH[base + 2] = {h[2], h[3]};
        *(__nv_bfloat162*)&g_meanL[base]     = {l[0], l[1]};
        *(__nv_bfloat162*)&g_meanL[base + 2] = {l[2], l[3]};
    }
}

// ---------------------------------------------------------------------------
// Misc prep: codebook split+norms (2048) | W1t split (512) | W2t split (512)
// ---------------------------------------------------------------------------
__global__ void __launch_bounds__(128) misc_prep_kernel(
    const float* __restrict__ codebook,
    const float* __restrict__ W1, const float* __restrict__ W2)
{
    __shared__ float ts[32][33];
    __shared__ float red[4];
    const int blk = blockIdx.x;
    const int t = threadIdx.x;

    if (blk < 2048) {
        int j = blk;
        float4 v = ((const float4*)codebook)[j * 128 + t];
        float vals[4] = {v.x, v.y, v.z, v.w};
        size_t base = (size_t)j * DD + t * 4;
        __nv_bfloat16 h[4], l[4];
        #pragma unroll
        for (int i = 0; i < 4; i++) split_bf16(vals[i], h[i], l[i]);
        *(__nv_bfloat162*)&g_cbH[base]     = {h[0], h[1]};
        *(__nv_bfloat162*)&g_cbH[base + 2] = {h[2], h[3]};
        *(__nv_bfloat162*)&g_cbL[base]     = {l[0], l[1]};
        *(__nv_bfloat162*)&g_cbL[base + 2] = {l[2], l[3]};

        float s = v.x * v.x + v.y * v.y + v.z * v.z + v.w * v.w;
        #pragma unroll
        for (int o = 16; o > 0; o >>= 1) s += __shfl_down_sync(0xffffffffu, s, o);
        if ((t & 31) == 0) red[t >> 5] = s;
        __syncthreads();
        if (t == 0) g_cnorm[j] = red[0] + red[1] + red[2] + red[3];
    } else {
        const float* W;
        __nv_bfloat16 *WtH, *WtL;
        int KD, ND, w;
        if (blk < 2560) {
            w = blk - 2048; W = W1; WtH = g_W1tH; WtL = g_W1tL; KD = DD; ND = HHID;
        } else {
            w = blk - 2560; W = W2; WtH = g_W2tH; WtL = g_W2tL; KD = HHID; ND = DD;
        }
        int nblk = ND / 32;
        int n0 = (w % nblk) * 32, k0 = (w / nblk) * 32;
        int tx = t & 31, ty = t >> 5;
        #pragma unroll
        for (int i = ty; i < 32; i += 4)
            ts[i][tx] = W[(size_t)(k0 + i) * ND + n0 + tx];
        __syncthreads();
        #pragma unroll
        for (int i = ty; i < 32; i += 4) {
            float v = ts[tx][i];
            __nv_bfloat16 h, l;
            split_bf16(v, h, l);
            size_t o = (size_t)(n0 + i) * KD + k0 + tx;
            WtH[o] = h;
            WtL[o] = l;
        }
    }
}

// ---------------------------------------------------------------------------
// Tensor-core GEMM (mma.sync bf16x3, fp32 accum): C = A[M,Kd] @ B[N,Kd]^T
// Identical math to R7; row0 selects the batch half.
// ---------------------------------------------------------------------------
template<int BM, int WHICH>
__global__ void __launch_bounds__(256, (BM == 64) ? 3 : 2) gemm_mma(
    const __nv_bfloat16* __restrict__ Ah, const __nv_bfloat16* __restrict__ Al,
    const __nv_bfloat16* __restrict__ Bh, const __nv_bfloat16* __restrict__ Bl,
    const float* __restrict__ bias, float* __restrict__ out_ue,
    int N, int Kd, int row0)
{
    constexpr int BN  = 64;
    constexpr int WM  = BM / 4;
    constexpr int MT  = WM / 16;
    constexpr int STAGE = 2 * (BM + BN) * 128;

    extern __shared__ char smem[];
    const uint32_t sbase = smem_u32(smem);
    const int tid  = threadIdx.x;
    const int lane = tid & 31;
    const int w    = tid >> 5;
    const int warp_m0 = (w >> 1) * WM;
    const int warp_n0 = (w & 1) * 32;
    const int bm = row0 + blockIdx.y * BM, bn = blockIdx.x * BN;

    auto loadT = [&](const __nv_bfloat16* __restrict__ src, int r0, int k0,
                     uint32_t dst, int R) {
        #pragma unroll 4
        for (int i = 0; i < R * 8; i += 256) {
            int u = tid + i;
            int r = u >> 3, c8 = u & 7;
            uint32_t sd = dst + r * 128 + ((c8 * 16) ^ ((r & 7) << 4));
            const __nv_bfloat16* gs = src + (size_t)(r0 + r) * Kd + k0 + c8 * 8;
            CP_ASYNC16(sd, gs);
        }
    };
    auto issue = [&](int c, int buf) {
        uint32_t sb = sbase + (uint32_t)buf * STAGE;
        int k0 = c * 64;
        loadT(Ah, bm, k0, sb, BM);
        loadT(Al, bm, k0, sb + BM * 128, BM);
        loadT(Bh, bn, k0, sb + 2 * BM * 128, BN);
        loadT(Bl, bn, k0, sb + 2 * BM * 128 + BN * 128, BN);
    };

    const int tile = lane >> 3, lr = lane & 7;
    const uint32_t xorp = (uint32_t)(lr << 4);
    const int aRow = warp_m0 + ((tile & 1) << 3) + lr;
    const uint32_t aK = (uint32_t)((tile >> 1) << 4);
    const int bRow = warp_n0 + ((tile >> 1) << 3) + lr;
    const uint32_t bK = (uint32_t)((tile & 1) << 4);

    float acc[MT][4][4] = {};

    const int NC = Kd / 64;
    issue(0, 0); CP_COMMIT();
    issue(1, 1); CP_COMMIT();
    CP_WAIT1();
    __syncthreads();

    for (int c = 0; c < NC; c++) {
        uint32_t s0 = sbase + (uint32_t)(c & 1) * STAGE;
        uint32_t pA[2] = { s0, s0 + BM * 128 };
        uint32_t pB[2] = { s0 + 2 * BM * 128, s0 + 2 * BM * 128 + BN * 128 };

        #pragma unroll
        for (int kk = 0; kk < 4; kk++) {
            uint32_t akb = (((uint32_t)kk << 5) + aK) ^ xorp;
            uint32_t bkb = (((uint32_t)kk << 5) + bK) ^ xorp;
            uint32_t a[2][MT][4];
            uint32_t b[2][4][2];
            #pragma unroll
            for (int s = 0; s < 2; s++)
                #pragma unroll
                for (int mt = 0; mt < MT; mt++)
                    ldsm4(a[s][mt], pA[s] + (uint32_t)(aRow + mt * 16) * 128 + akb);
            #pragma unroll
            for (int s = 0; s < 2; s++)
                #pragma unroll
                for (int ng = 0; ng < 2; ng++) {
                    uint32_t t4[4];
                    ldsm4(t4, pB[s] + (uint32_t)(bRow + ng * 16) * 128 + bkb);
                    b[s][2 * ng][0] = t4[0]; b[s][2 * ng][1] = t4[1];
                    b[s][2 * ng + 1][0] = t4[2]; b[s][2 * ng + 1][1] = t4[3];
                }
            #pragma unroll
            for (int mt = 0; mt < MT; mt++)
                #pragma unroll
                for (int nt = 0; nt < 4; nt++)
                    mma16816(acc[mt][nt], a[0][mt], b[0][nt][0], b[0][nt][1]);
            #pragma unroll
            for (int mt = 0; mt < MT; mt++)
                #pragma unroll
                for (int nt = 0; nt < 4; nt++)
                    mma16816(acc[mt][nt], a[0][mt], b[1][nt][0], b[1][nt][1]);
            #pragma unroll
            for (int mt = 0; mt < MT; mt++)
                #pragma unroll
                for (int nt = 0; nt < 4; nt++)
                    mma16816(acc[mt][nt], a[1][mt], b[0][nt][0], b[0][nt][1]);
        }

        if (c == NC - 1) break;
        __syncthreads();
        if (c + 2 < NC) { issue(c + 2, c & 1); CP_COMMIT(); CP_WAIT1(); }
        else            { CP_WAIT0(); }
        __syncthreads();
    }

    const int lr4 = lane >> 2;
    const int lc2 = (lane & 3) * 2;

    if (WHICH == 2) {
        int chunk = (bn + warp_n0) >> 5;
        #pragma unroll
        for (int mt = 0; mt < MT; mt++)
            #pragma unroll
            for (int half = 0; half < 2; half++) {
                int row = bm + warp_m0 + mt * 16 + lr4 + half * 8;
                float mv = 3.0e38f; int mj = 0x7fffffff;
                #pragma unroll
                for (int nt = 0; nt < 4; nt++) {
                    int col = bn + warp_n0 + nt * 8 + lc2;
                    float2 cn = *(const float2*)&g_cnorm[col];
                    float s0 = cn.x - 2.0f * acc[mt][nt][half * 2 + 0];
                    float s1 = cn.y - 2.0f * acc[mt][nt][half * 2 + 1];
                    if (s0 < mv) { mv = s0; mj = col; }
                    if (s1 < mv) { mv = s1; mj = col + 1; }
                }
                #pragma unroll
                for (int o = 1; o < 4; o <<= 1) {
                    float ov = __shfl_xor_sync(0xffffffffu, mv, o);
                    int   oj = __shfl_xor_sync(0xffffffffu, mj, o);
                    if (ov < mv || (ov == mv && oj < mj)) { mv = ov; mj = oj; }
                }
                if ((lane & 3) == 0) {
                    g_pval[(size_t)row * NBW + chunk] = mv;
                    g_pidx[(size_t)row * NBW + chunk] = mj;
                }
            }
    } else {
        #pragma unroll
        for (int mt = 0; mt < MT; mt++)
            #pragma unroll
            for (int half = 0; half < 2; half++) {
                int row = bm + warp_m0 + mt * 16 + lr4 + half * 8;
                #pragma unroll
                for (int nt = 0; nt < 4; nt++) {
                    int col = bn + warp_n0 + nt * 8 + lc2;
                    float2 bv = *(const float2*)&bias[col];
                    float v0 = acc[mt][nt][half * 2 + 0] + bv.x;
                    float v1 = acc[mt][nt][half * 2 + 1] + bv.y;
                    size_t o = (size_t)row * N + col;
                    if (WHICH == 0) {
                        v0 = fmaxf(v0, 0.f); v1 = fmaxf(v1, 0.f);
                        __nv_bfloat16 h0, l0, h1, l1;
                        split_bf16(v0, h0, l0); split_bf16(v1, h1, l1);
                        *(__nv_bfloat162*)&g_hidH[o] = {h0, h1};
                        *(__nv_bfloat162*)&g_hidL[o] = {l0, l1};
                    } else {
                        *(float2*)&g_u[o] = make_float2(v0, v1);
                        out_ue[o] = v0; out_ue[o + 1] = v1;
                        __nv_bfloat16 h0, l0, h1, l1;
                        split_bf16(v0, h0, l0); split_bf16(v1, h1, l1);
                        *(__nv_bfloat162*)&g_uH[o] = {h0, h1};
                        *(__nv_bfloat162*)&g_uL[o] = {l0, l1};
                    }
                }
            }
    }
}

// ---------------------------------------------------------------------------
// Epilogue for one half (grid = HB): final argmin over 64 partials, VQ
// outputs, pos/neg gathers, diff partials; last block overall does the
// fixed-tree diff reduction and resets the counter for graph replay.
// ---------------------------------------------------------------------------
__global__ void __launch_bounds__(128) epilogue_kernel(
    const float* __restrict__ codebook, const float* __restrict__ item_embed,
    const int* __restrict__ pos, const int* __restrict__ neg,
    float* __restrict__ out_q, float* __restrict__ out_pos,
    float* __restrict__ out_neg, float* __restrict__ out_diff, int row0)
{
    int b = row0 + blockIdx.x;
    int t = threadIdx.x;

    __shared__ float pv[64];
    __shared__ int   pi[64];
    __shared__ int   s_id;
    __shared__ bool  s_last;
    if (t < 64) {
        pv[t] = g_pval[(size_t)b * NBW + t];
        pi[t] = g_pidx[(size_t)b * NBW + t];
    }
    __syncthreads();
    if (t < 32) {
        float v1 = pv[t]; int i1 = pi[t];
        float v2 = pv[t + 32]; int i2 = pi[t + 32];
        if (v2 < v1 || (v2 == v1 && i2 < i1)) { v1 = v2; i1 = i2; }
        #pragma unroll
        for (int o = 16; o > 0; o >>= 1) {
            float ov = __shfl_down_sync(0xffffffffu, v1, o);
            int   oi = __shfl_down_sync(0xffffffffu, i1, o);
            if (ov < v1 || (ov == v1 && oi < i1)) { v1 = ov; i1 = oi; }
        }
        if (t == 0) s_id = i1;
    }
    __syncthreads();
    int id = s_id;

    float4 q = ((const float4*)codebook)[(size_t)id * 128 + t];
    float4 u = ((const float4*)g_u)[(size_t)b * 128 + t];
    float4 d = make_float4(q.x - u.x, q.y - u.y, q.z - u.z, q.w - u.w);
    float4 qu = make_float4(u.x + d.x, u.y + d.y, u.z + d.z, u.w + d.w);
    ((float4*)out_q)[(size_t)b * 128 + t] = qu;

    int p = pos[b], n = neg[b];
    ((float4*)out_pos)[(size_t)b * 128 + t] = ((const float4*)item_embed)[(size_t)p * 128 + t];
    ((float4*)out_neg)[(size_t)b * 128 + t] = ((const float4*)item_embed)[(size_t)n * 128 + t];

    float ds = d.x * d.x + d.y * d.y + d.z * d.z + d.w * d.w;
    #pragma unroll
    for (int o = 16; o > 0; o >>= 1) ds += __shfl_down_sync(0xffffffffu, ds, o);
    __shared__ float red[4];
    if ((t & 31) == 0) red[t >> 5] = ds;
    __syncthreads();
    if (t == 0) {
        g_bsum[b] = red[0] + red[1] + red[2] + red[3];
        __threadfence();
        int c = atomicAdd(&g_count, 1);
        s_last = (c == BB - 1);
    }
    __syncthreads();

    if (s_last) {
        __threadfence();
        float s = 0.f;
        #pragma unroll
        for (int i = 0; i < BB / 128; i++) s += g_bsum[t + i * 128];
        __shared__ float sv[128];
        sv[t] = s;
        __syncthreads();
        for (int o = 64; o > 0; o >>= 1) {
            if (t < o) sv[t] += sv[t + o];
            __syncthreads();
        }
        if (t == 0) {
            *out_diff = sv[0] * (1.0f / (float)BD);
            g_count = 0;                       // reset for next graph replay
        }
    }
}

// ---------------------------------------------------------------------------
extern "C" void kernel_launch(void* const* d_in, const int* in_sizes, int n_in,
                              void* d_out, int out_size)
{
    const int*   items      = (const int*)  d_in[1];
    const int*   pos        = (const int*)  d_in[2];
    const int*   neg        = (const int*)  d_in[3];
    const float* item_embed = (const float*)d_in[4];
    const float* W1         = (const float*)d_in[5];
    const float* b1         = (const float*)d_in[6];
    const float* W2         = (const float*)d_in[7];
    const float* b2         = (const float*)d_in[8];
    const float* codebook   = (const float*)d_in[9];

    float* out      = (float*)d_out;
    float* out_q    = out;
    float* out_pos  = out + (size_t)BD;
    float* out_neg  = out + (size_t)2 * BD;
    float* out_diff = out + (size_t)3 * BD;
    float* out_ue   = out + (size_t)3 * BD + 1;

    const int SMEM_128 = 2 * 2 * (128 + 64) * 128;  // 98304
    const int SMEM_64  = 2 * 2 * (64 + 64) * 128;   // 65536

    // One-time setup on the first (uncaptured, correctness) call.
    static cudaStream_t s1 = nullptr;
    static cudaEvent_t evFork = nullptr, evMisc = nullptr, evG0 = nullptr, evEnd1 = nullptr;
    if (s1 == nullptr) {
        cudaFuncSetAttribute((const void*)gemm_mma<128, 0>,
                             cudaFuncAttributeMaxDynamicSharedMemorySize, SMEM_128);
        cudaFuncSetAttribute((const void*)gemm_mma<64, 1>,
                             cudaFuncAttributeMaxDynamicSharedMemorySize, SMEM_64);
        cudaFuncSetAttribute((const void*)gemm_mma<128, 2>,
                             cudaFuncAttributeMaxDynamicSharedMemorySize, SMEM_128);
        cudaStreamCreateWithFlags(&s1, cudaStreamNonBlocking);
        cudaEventCreateWithFlags(&evFork, cudaEventDisableTiming);
        cudaEventCreateWithFlags(&evMisc, cudaEventDisableTiming);
        cudaEventCreateWithFlags(&evG0,   cudaEventDisableTiming);
        cudaEventCreateWithFlags(&evEnd1, cudaEventDisableTiming);
    }

    __nv_bfloat16 *meanH, *meanL, *hidH, *hidL, *uH, *uL, *w1tH, *w1tL, *w2tH, *w2tL, *cbH, *cbL;
    cudaGetSymbolAddress((void**)&meanH, g_meanH);
    cudaGetSymbolAddress((void**)&meanL, g_meanL);
    cudaGetSymbolAddress((void**)&hidH,  g_hidH);
    cudaGetSymbolAddress((void**)&hidL,  g_hidL);
    cudaGetSymbolAddress((void**)&uH,    g_uH);
    cudaGetSymbolAddress((void**)&uL,    g_uL);
    cudaGetSymbolAddress((void**)&w1tH,  g_W1tH);
    cudaGetSymbolAddress((void**)&w1tL,  g_W1tL);
    cudaGetSymbolAddress((void**)&w2tH,  g_W2tH);
    cudaGetSymbolAddress((void**)&w2tL,  g_W2tL);
    cudaGetSymbolAddress((void**)&cbH,   g_cbH);
    cudaGetSymbolAddress((void**)&cbL,   g_cbL);

    // ---- fork: s1 runs misc prep concurrently with gather(h0) on stream 0 ----
    cudaEventRecord(evFork, 0);
    cudaStreamWaitEvent(s1, evFork, 0);
    misc_prep_kernel<<<3072, 128, 0, s1>>>(codebook, W1, W2);
    cudaEventRecord(evMisc, s1);

    gather_kernel<<<GBLK, 256>>>(items, item_embed, 0);      // stream 0: half 0
    cudaEventRecord(evG0, 0);
    cudaStreamWaitEvent(s1, evG0, 0);

    // ---- s1: half-0 GEMM chain + epilogue (co-resident with gather(h1)) ----
    gemm_mma<128, 0><<<dim3(HHID / 64, HB / 128), 256, SMEM_128, s1>>>(
        meanH, meanL, w1tH, w1tL, b1, nullptr, HHID, DD, 0);
    gemm_mma<64, 1><<<dim3(DD / 64, HB / 64), 256, SMEM_64, s1>>>(
        hidH,  hidL,  w2tH, w2tL, b2, out_ue,  DD,  HHID, 0);
    gemm_mma<128, 2><<<dim3(CBK / 64, HB / 128), 256, SMEM_128, s1>>>(
        uH,    uL,    cbH,  cbL,  nullptr, nullptr, CBK, DD, 0);
    epilogue_kernel<<<HB, 128, 0, s1>>>(codebook, item_embed, pos, neg,
                                        out_q, out_pos, out_neg, out_diff, 0);
    cudaEventRecord(evEnd1, s1);

    // ---- stream 0: gather(h1) co-runs with the h0 chain; then h1 chain ----
    gather_kernel<<<GBLK, 256>>>(items, item_embed, HB);
    cudaStreamWaitEvent(0, evMisc, 0);   // W/cb splits ready before gemm0(h1)
    gemm_mma<128, 0><<<dim3(HHID / 64, HB / 128), 256, SMEM_128>>>(
        meanH, meanL, w1tH, w1tL, b1, nullptr, HHID, DD, HB);
    gemm_mma<64, 1><<<dim3(DD / 64, HB / 64), 256, SMEM_64>>>(
        hidH,  hidL,  w2tH, w2tL, b2, out_ue,  DD,  HHID, HB);
    gemm_mma<128, 2><<<dim3(CBK / 64, HB / 128), 256, SMEM_128>>>(
        uH,    uL,    cbH,  cbL,  nullptr, nullptr, CBK, DD, HB);
    epilogue_kernel<<<HB, 128>>>(codebook, item_embed, pos, neg,
                                 out_q, out_pos, out_neg, out_diff, HB);

    // ---- join s1 back into stream 0 ----
    cudaStreamWaitEvent(0, evEnd1, 0);
}

// round 12
// speedup vs baseline: 1.4120x; 1.4118x over previous
#include <cuda_runtime.h>
#include <cuda_bf16.h>
#include <cstdint>

// Problem constants
#define BB    2048     // batch
#define KHIST 200      // history length
#define DD    512      // latent dim
#define HHID  1024     // 2*D
#define CBK   2048     // codebook size
#define BD    (BB*DD)  // 1048576
#define NBW   64       // CBK / 32 argmin partial chunks per row
#define TH    50000    // item-id threshold: pass A < TH, pass B >= TH

// ---------------- scratch (device globals; no allocation allowed) ----------
__device__ float        g_u[BB * DD];
__device__ float        g_cnorm[CBK];
__device__ float        g_pval[BB * NBW];
__device__ int          g_pidx[BB * NBW];
__device__ float        g_bsum[BB];
__device__ int          g_count;          // zero-init; self-resetting
__device__ float        g_macc[BB * DD];  // fp32 partial mean accumulator (pass A)
__device__ int          g_mcnt[BB];       // partial counts (pass A)

// bf16 hi/lo split operands
__device__ __nv_bfloat16 g_meanH[BB * DD],   g_meanL[BB * DD];
__device__ __nv_bfloat16 g_hidH [BB * HHID], g_hidL [BB * HHID];
__device__ __nv_bfloat16 g_uH   [BB * DD],   g_uL   [BB * DD];
__device__ __nv_bfloat16 g_W1tH [HHID * DD], g_W1tL [HHID * DD];
__device__ __nv_bfloat16 g_W2tH [DD * HHID], g_W2tL [DD * HHID];
__device__ __nv_bfloat16 g_cbH  [CBK * DD],  g_cbL  [CBK * DD];

// ---------------------------------------------------------------------------
// Portable PTX helpers (sm_80+; ptxas targets plain sm_103 — no tcgen05)
// ---------------------------------------------------------------------------
__device__ __forceinline__ uint32_t smem_u32(const void* p) {
    uint32_t a;
    asm("{ .reg .u64 t; cvta.to.shared.u64 t, %1; cvt.u32.u64 %0, t; }" : "=r"(a) : "l"(p));
    return a;
}

#define CP_ASYNC16(dst, src) \
    asm volatile("cp.async.cg.shared.global [%0], [%1], 16;" :: "r"(dst), "l"(src))
#define CP_COMMIT() asm volatile("cp.async.commit_group;" ::: "memory")
#define CP_WAIT0()  asm volatile("cp.async.wait_group 0;" ::: "memory")
#define CP_WAIT1()  asm volatile("cp.async.wait_group 1;" ::: "memory")

__device__ __forceinline__ void ldsm4(uint32_t (&r)[4], uint32_t addr) {
    asm volatile("ldmatrix.sync.aligned.m8n8.x4.shared.b16 {%0,%1,%2,%3}, [%4];"
                 : "=r"(r[0]), "=r"(r[1]), "=r"(r[2]), "=r"(r[3]) : "r"(addr));
}

__device__ __forceinline__ void mma16816(float (&d)[4], const uint32_t (&a)[4],
                                         uint32_t b0, uint32_t b1) {
    asm volatile(
        "mma.sync.aligned.m16n8k16.row.col.f32.bf16.bf16.f32 "
        "{%0,%1,%2,%3}, {%4,%5,%6,%7}, {%8,%9}, {%0,%1,%2,%3};"
        : "+f"(d[0]), "+f"(d[1]), "+f"(d[2]), "+f"(d[3])
        : "r"(a[0]), "r"(a[1]), "r"(a[2]), "r"(a[3]), "r"(b0), "r"(b1));
}

__device__ __forceinline__ void split_bf16(float v, __nv_bfloat16& h, __nv_bfloat16& l) {
    h = __float2bfloat16(v);
    l = __float2bfloat16(v - __bfloat162float(h));
}

// ---------------------------------------------------------------------------
// PREP pass A (5120 blocks x 128 thr):
//   blocks [0,2048)    : gather items in (0, TH) -> fp32 partial acc + count
//   blocks [2048,4096) : codebook norms + hi/lo split
//   blocks [4096,4608) : W1^T hi/lo split
//   blocks [4608,5120) : W2^T hi/lo split
// Pass A's unique item working set (~102 MB) fits L2 -> first-touch-only misses.
// ---------------------------------------------------------------------------
__global__ void __launch_bounds__(128) prepA_kernel(
    const int* __restrict__ items, const float* __restrict__ item_embed,
    const float* __restrict__ codebook,
    const float* __restrict__ W1, const float* __restrict__ W2)
{
    __shared__ int   sidx[KHIST];
    __shared__ float ts[32][33];
    __shared__ float red[4];

    const int blk = blockIdx.x;
    const int t = threadIdx.x;

    if (blk < 2048) {
        int b = blk;
        for (int i = t; i < KHIST; i += 128) sidx[i] = items[b * KHIST + i];
        __syncthreads();
        const float4* E4 = (const float4*)item_embed;
        float4 acc = make_float4(0.f, 0.f, 0.f, 0.f);
        int cnt = 0;
        #pragma unroll 4
        for (int k = 0; k < KHIST; k++) {
            int idx = sidx[k];
            if (idx != 0 && idx < TH) {       // uniform across the block
                float4 v = E4[(size_t)idx * 128 + t];
                acc.x += v.x; acc.y += v.y; acc.z += v.z; acc.w += v.w;
                cnt++;
            }
        }
        ((float4*)g_macc)[(size_t)b * 128 + t] = acc;
        if (t == 0) g_mcnt[b] = cnt;
    } else if (blk < 4096) {
        int j = blk - 2048;
        float4 v = ((const float4*)codebook)[j * 128 + t];
        float vals[4] = {v.x, v.y, v.z, v.w};
        size_t base = (size_t)j * DD + t * 4;
        __nv_bfloat16 h[4], l[4];
        #pragma unroll
        for (int i = 0; i < 4; i++) split_bf16(vals[i], h[i], l[i]);
        *(__nv_bfloat162*)&g_cbH[base]     = {h[0], h[1]};
        *(__nv_bfloat162*)&g_cbH[base + 2] = {h[2], h[3]};
        *(__nv_bfloat162*)&g_cbL[base]     = {l[0], l[1]};
        *(__nv_bfloat162*)&g_cbL[base + 2] = {l[2], l[3]};

        float s = v.x * v.x + v.y * v.y + v.z * v.z + v.w * v.w;
        #pragma unroll
        for (int o = 16; o > 0; o >>= 1) s += __shfl_down_sync(0xffffffffu, s, o);
        if ((t & 31) == 0) red[t >> 5] = s;
        __syncthreads();
        if (t == 0) g_cnorm[j] = red[0] + red[1] + red[2] + red[3];
    } else {
        const float* W;
        __nv_bfloat16 *WtH, *WtL;
        int KD, ND, w;
        if (blk < 4608) {
            w = blk - 4096; W = W1; WtH = g_W1tH; WtL = g_W1tL; KD = DD; ND = HHID;
        } else {
            w = blk - 4608; W = W2; WtH = g_W2tH; WtL = g_W2tL; KD = HHID; ND = DD;
        }
        int nblk = ND / 32;
        int n0 = (w % nblk) * 32, k0 = (w / nblk) * 32;
        int tx = t & 31, ty = t >> 5;
        #pragma unroll
        for (int i = ty; i < 32; i += 4)
            ts[i][tx] = W[(size_t)(k0 + i) * ND + n0 + tx];
        __syncthreads();
        #pragma unroll
        for (int i = ty; i < 32; i += 4) {
            float v = ts[tx][i];
            __nv_bfloat16 h, l;
            split_bf16(v, h, l);
            size_t o = (size_t)(n0 + i) * KD + k0 + tx;
            WtH[o] = h;
            WtL[o] = l;
        }
    }
}

// ---------------------------------------------------------------------------
// PREP pass B (2048 blocks x 128 thr): gather items >= TH (upper ~104 MB of
// the table), combine with pass-A partials, finalize mean, bf16 hi/lo split.
// ---------------------------------------------------------------------------
__global__ void __launch_bounds__(128) prepB_kernel(
    const int* __restrict__ items, const float* __restrict__ item_embed)
{
    __shared__ int sidx[KHIST];
    const int b = blockIdx.x;
    const int t = threadIdx.x;
    for (int i = t; i < KHIST; i += 128) sidx[i] = items[b * KHIST + i];
    __syncthreads();

    const float4* E4 = (const float4*)item_embed;
    float4 acc = ((const float4*)g_macc)[(size_t)b * 128 + t];
    int cnt = g_mcnt[b];
    #pragma unroll 4
    for (int k = 0; k < KHIST; k++) {
        int idx = sidx[k];
        if (idx >= TH) {                      // uniform across the block
            float4 v = E4[(size_t)idx * 128 + t];
            acc.x += v.x; acc.y += v.y; acc.z += v.z; acc.w += v.w;
            cnt++;
        }
    }
    float inv = 1.0f / (float)cnt;
    float vals[4] = {acc.x * inv, acc.y * inv, acc.z * inv, acc.w * inv};
    size_t base = (size_t)b * DD + t * 4;
    __nv_bfloat16 h[4], l[4];
    #pragma unroll
    for (int i = 0; i < 4; i++) split_bf16(vals[i], h[i], l[i]);
    *(__nv_bfloat162*)&g_meanH[base]     = {h[0], h[1]};
    *(__nv_bfloat162*)&g_meanH[base + 2] = {h[2], h[3]};
    *(__nv_bfloat162*)&g_meanL[base]     = {l[0], l[1]};
    *(__nv_bfloat162*)&g_meanL[base + 2] = {l[2], l[3]};
}

// ---------------------------------------------------------------------------
// Tensor-core GEMM (mma.sync bf16x3, fp32 accum): C = A[M,Kd] @ B[N,Kd]^T
// BM x 64 CTA tile, 8 warps (4x2), K-chunks of 64 halves, SW128-swizzled
// smem, 2-stage cp.async, multi-CTA/SM residency.  (identical to R7)
// WHICH=0: hid = relu(mean @ W1t^T + b1)  BM=128
// WHICH=1: u   = hid @ W2t^T + b2         BM=64   (+ out_ue)
// WHICH=2: fused scores+argmin partials   BM=128
// ---------------------------------------------------------------------------
template<int BM, int WHICH>
__global__ void __launch_bounds__(256, (BM == 64) ? 3 : 2) gemm_mma(
    const __nv_bfloat16* __restrict__ Ah, const __nv_bfloat16* __restrict__ Al,
    const __nv_bfloat16* __restrict__ Bh, const __nv_bfloat16* __restrict__ Bl,
    const float* __restrict__ bias, float* __restrict__ out_ue,
    int N, int Kd)
{
    constexpr int BN  = 64;
    constexpr int WM  = BM / 4;
    constexpr int MT  = WM / 16;
    constexpr int STAGE = 2 * (BM + BN) * 128;

    extern __shared__ char smem[];
    const uint32_t sbase = smem_u32(smem);
    const int tid  = threadIdx.x;
    const int lane = tid & 31;
    const int w    = tid >> 5;
    const int warp_m0 = (w >> 1) * WM;
    const int warp_n0 = (w & 1) * 32;
    const int bm = blockIdx.y * BM, bn = blockIdx.x * BN;

    auto loadT = [&](const __nv_bfloat16* __restrict__ src, int row0, int k0,
                     uint32_t dst, int R) {
        #pragma unroll 4
        for (int i = 0; i < R * 8; i += 256) {
            int u = tid + i;
            int r = u >> 3, c8 = u & 7;
            uint32_t sd = dst + r * 128 + ((c8 * 16) ^ ((r & 7) << 4));
            const __nv_bfloat16* gs = src + (size_t)(row0 + r) * Kd + k0 + c8 * 8;
            CP_ASYNC16(sd, gs);
        }
    };
    auto issue = [&](int c, int buf) {
        uint32_t sb = sbase + (uint32_t)buf * STAGE;
        int k0 = c * 64;
        loadT(Ah, bm, k0, sb, BM);
        loadT(Al, bm, k0, sb + BM * 128, BM);
        loadT(Bh, bn, k0, sb + 2 * BM * 128, BN);
        loadT(Bl, bn, k0, sb + 2 * BM * 128 + BN * 128, BN);
    };

    const int tile = lane >> 3, lr = lane & 7;
    const uint32_t xorp = (uint32_t)(lr << 4);
    const int aRow = warp_m0 + ((tile & 1) << 3) + lr;
    const uint32_t aK = (uint32_t)((tile >> 1) << 4);
    const int bRow = warp_n0 + ((tile >> 1) << 3) + lr;
    const uint32_t bK = (uint32_t)((tile & 1) << 4);

    float acc[MT][4][4] = {};

    const int NC = Kd / 64;
    issue(0, 0); CP_COMMIT();
    issue(1, 1); CP_COMMIT();
    CP_WAIT1();
    __syncthreads();

    for (int c = 0; c < NC; c++) {
        uint32_t s0 = sbase + (uint32_t)(c & 1) * STAGE;
        uint32_t pA[2] = { s0, s0 + BM * 128 };
        uint32_t pB[2] = { s0 + 2 * BM * 128, s0 + 2 * BM * 128 + BN * 128 };

        #pragma unroll
        for (int kk = 0; kk < 4; kk++) {
            uint32_t akb = (((uint32_t)kk << 5) + aK) ^ xorp;
            uint32_t bkb = (((uint32_t)kk << 5) + bK) ^ xorp;
            uint32_t a[2][MT][4];
            uint32_t b[2][4][2];
            #pragma unroll
            for (int s = 0; s < 2; s++)
                #pragma unroll
                for (int mt = 0; mt < MT; mt++)
                    ldsm4(a[s][mt], pA[s] + (uint32_t)(aRow + mt * 16) * 128 + akb);
            #pragma unroll
            for (int s = 0; s < 2; s++)
                #pragma unroll
                for (int ng = 0; ng < 2; ng++) {
                    uint32_t t4[4];
                    ldsm4(t4, pB[s] + (uint32_t)(bRow + ng * 16) * 128 + bkb);
                    b[s][2 * ng][0] = t4[0]; b[s][2 * ng][1] = t4[1];
                    b[s][2 * ng + 1][0] = t4[2]; b[s][2 * ng + 1][1] = t4[3];
                }
            #pragma unroll
            for (int mt = 0; mt < MT; mt++)
                #pragma unroll
                for (int nt = 0; nt < 4; nt++)
                    mma16816(acc[mt][nt], a[0][mt], b[0][nt][0], b[0][nt][1]);
            #pragma unroll
            for (int mt = 0; mt < MT; mt++)
                #pragma unroll
                for (int nt = 0; nt < 4; nt++)
                    mma16816(acc[mt][nt], a[0][mt], b[1][nt][0], b[1][nt][1]);
            #pragma unroll
            for (int mt = 0; mt < MT; mt++)
                #pragma unroll
                for (int nt = 0; nt < 4; nt++)
                    mma16816(acc[mt][nt], a[1][mt], b[0][nt][0], b[0][nt][1]);
        }

        if (c == NC - 1) break;
        __syncthreads();
        if (c + 2 < NC) { issue(c + 2, c & 1); CP_COMMIT(); CP_WAIT1(); }
        else            { CP_WAIT0(); }
        __syncthreads();
    }

    const int lr4 = lane >> 2;
    const int lc2 = (lane & 3) * 2;

    if (WHICH == 2) {
        int chunk = (bn + warp_n0) >> 5;
        #pragma unroll
        for (int mt = 0; mt < MT; mt++)
            #pragma unroll
            for (int half = 0; half < 2; half++) {
                int row = bm + warp_m0 + mt * 16 + lr4 + half * 8;
                float mv = 3.0e38f; int mj = 0x7fffffff;
                #pragma unroll
                for (int nt = 0; nt < 4; nt++) {
                    int col = bn + warp_n0 + nt * 8 + lc2;
                    float2 cn = *(const float2*)&g_cnorm[col];
                    float s0 = cn.x - 2.0f * acc[mt][nt][half * 2 + 0];
                    float s1 = cn.y - 2.0f * acc[mt][nt][half * 2 + 1];
                    if (s0 < mv) { mv = s0; mj = col; }
                    if (s1 < mv) { mv = s1; mj = col + 1; }
                }
                #pragma unroll
                for (int o = 1; o < 4; o <<= 1) {
                    float ov = __shfl_xor_sync(0xffffffffu, mv, o);
                    int   oj = __shfl_xor_sync(0xffffffffu, mj, o);
                    if (ov < mv || (ov == mv && oj < mj)) { mv = ov; mj = oj; }
                }
                if ((lane & 3) == 0) {
                    g_pval[(size_t)row * NBW + chunk] = mv;
                    g_pidx[(size_t)row * NBW + chunk] = mj;
                }
            }
    } else {
        #pragma unroll
        for (int mt = 0; mt < MT; mt++)
            #pragma unroll
            for (int half = 0; half < 2; half++) {
                int row = bm + warp_m0 + mt * 16 + lr4 + half * 8;
                #pragma unroll
                for (int nt = 0; nt < 4; nt++) {
                    int col = bn + warp_n0 + nt * 8 + lc2;
                    float2 bv = *(const float2*)&bias[col];
                    float v0 = acc[mt][nt][half * 2 + 0] + bv.x;
                    float v1 = acc[mt][nt][half * 2 + 1] + bv.y;
                    size_t o = (size_t)row * N + col;
                    if (WHICH == 0) {
                        v0 = fmaxf(v0, 0.f); v1 = fmaxf(v1, 0.f);
                        __nv_bfloat16 h0, l0, h1, l1;
                        split_bf16(v0, h0, l0); split_bf16(v1, h1, l1);
                        *(__nv_bfloat162*)&g_hidH[o] = {h0, h1};
                        *(__nv_bfloat162*)&g_hidL[o] = {l0, l1};
                    } else {
                        *(float2*)&g_u[o] = make_float2(v0, v1);
                        out_ue[o] = v0; out_ue[o + 1] = v1;
                        __nv_bfloat16 h0, l0, h1, l1;
                        split_bf16(v0, h0, l0); split_bf16(v1, h1, l1);
                        *(__nv_bfloat162*)&g_uH[o] = {h0, h1};
                        *(__nv_bfloat162*)&g_uL[o] = {l0, l1};
                    }
                }
            }
    }
}

// ---------------------------------------------------------------------------
// Fused epilogue: per-row final argmin over 64 partials, VQ outputs, pos/neg
// gathers, diff partials; last block does the fixed-tree diff reduction and
// resets the counter for graph replay.  (identical to R7)
// ---------------------------------------------------------------------------
__global__ void __launch_bounds__(128) epilogue_kernel(
    const float* __restrict__ codebook, const float* __restrict__ item_embed,
    const int* __restrict__ pos, const int* __restrict__ neg,
    float* __restrict__ out_q, float* __restrict__ out_pos,
    float* __restrict__ out_neg, float* __restrict__ out_diff)
{
    int b = blockIdx.x;
    int t = threadIdx.x;

    __shared__ float pv[64];
    __shared__ int   pi[64];
    __shared__ int   s_id;
    __shared__ bool  s_last;
    if (t < 64) {
        pv[t] = g_pval[(size_t)b * NBW + t];
        pi[t] = g_pidx[(size_t)b * NBW + t];
    }
    __syncthreads();
    if (t < 32) {
        float v1 = pv[t]; int i1 = pi[t];
        float v2 = pv[t + 32]; int i2 = pi[t + 32];
        if (v2 < v1 || (v2 == v1 && i2 < i1)) { v1 = v2; i1 = i2; }
        #pragma unroll
        for (int o = 16; o > 0; o >>= 1) {
            float ov = __shfl_down_sync(0xffffffffu, v1, o);
            int   oi = __shfl_down_sync(0xffffffffu, i1, o);
            if (ov < v1 || (ov == v1 && oi < i1)) { v1 = ov; i1 = oi; }
        }
        if (t == 0) s_id = i1;
    }
    __syncthreads();
    int id = s_id;

    float4 q = ((const float4*)codebook)[(size_t)id * 128 + t];
    float4 u = ((const float4*)g_u)[(size_t)b * 128 + t];
    float4 d = make_float4(q.x - u.x, q.y - u.y, q.z - u.z, q.w - u.w);
    float4 qu = make_float4(u.x + d.x, u.y + d.y, u.z + d.z, u.w + d.w);
    ((float4*)out_q)[(size_t)b * 128 + t] = qu;

    int p = pos[b], n = neg[b];
    ((float4*)out_pos)[(size_t)b * 128 + t] = ((const float4*)item_embed)[(size_t)p * 128 + t];
    ((float4*)out_neg)[(size_t)b * 128 + t] = ((const float4*)item_embed)[(size_t)n * 128 + t];

    float ds = d.x * d.x + d.y * d.y + d.z * d.z + d.w * d.w;
    #pragma unroll
    for (int o = 16; o > 0; o >>= 1) ds += __shfl_down_sync(0xffffffffu, ds, o);
    __shared__ float red[4];
    if ((t & 31) == 0) red[t >> 5] = ds;
    __syncthreads();
    if (t == 0) {
        g_bsum[b] = red[0] + red[1] + red[2] + red[3];
        __threadfence();
        int c = atomicAdd(&g_count, 1);
        s_last = (c == BB - 1);
    }
    __syncthreads();

    if (s_last) {
        __threadfence();
        float s = 0.f;
        #pragma unroll
        for (int i = 0; i < BB / 128; i++) s += g_bsum[t + i * 128];
        __shared__ float sv[128];
        sv[t] = s;
        __syncthreads();
        for (int o = 64; o > 0; o >>= 1) {
            if (t < o) sv[t] += sv[t + o];
            __syncthreads();
        }
        if (t == 0) {
            *out_diff = sv[0] * (1.0f / (float)BD);
            g_count = 0;                       // reset for next graph replay
        }
    }
}

// ---------------------------------------------------------------------------
extern "C" void kernel_launch(void* const* d_in, const int* in_sizes, int n_in,
                              void* d_out, int out_size)
{
    const int*   items      = (const int*)  d_in[1];
    const int*   pos        = (const int*)  d_in[2];
    const int*   neg        = (const int*)  d_in[3];
    const float* item_embed = (const float*)d_in[4];
    const float* W1         = (const float*)d_in[5];
    const float* b1         = (const float*)d_in[6];
    const float* W2         = (const float*)d_in[7];
    const float* b2         = (const float*)d_in[8];
    const float* codebook   = (const float*)d_in[9];

    float* out      = (float*)d_out;
    float* out_q    = out;
    float* out_pos  = out + (size_t)BD;
    float* out_neg  = out + (size_t)2 * BD;
    float* out_diff = out + (size_t)3 * BD;
    float* out_ue   = out + (size_t)3 * BD + 1;

    const int SMEM_128 = 2 * 2 * (128 + 64) * 128;  // 98304
    const int SMEM_64  = 2 * 2 * (64 + 64) * 128;   // 65536
    cudaFuncSetAttribute((const void*)gemm_mma<128, 0>,
                         cudaFuncAttributeMaxDynamicSharedMemorySize, SMEM_128);
    cudaFuncSetAttribute((const void*)gemm_mma<64, 1>,
                         cudaFuncAttributeMaxDynamicSharedMemorySize, SMEM_64);
    cudaFuncSetAttribute((const void*)gemm_mma<128, 2>,
                         cudaFuncAttributeMaxDynamicSharedMemorySize, SMEM_128);

    __nv_bfloat16 *meanH, *meanL, *hidH, *hidL, *uH, *uL, *w1tH, *w1tL, *w2tH, *w2tL, *cbH, *cbL;
    cudaGetSymbolAddress((void**)&meanH, g_meanH);
    cudaGetSymbolAddress((void**)&meanL, g_meanL);
    cudaGetSymbolAddress((void**)&hidH,  g_hidH);
    cudaGetSymbolAddress((void**)&hidL,  g_hidL);
    cudaGetSymbolAddress((void**)&uH,    g_uH);
    cudaGetSymbolAddress((void**)&uL,    g_uL);
    cudaGetSymbolAddress((void**)&w1tH,  g_W1tH);
    cudaGetSymbolAddress((void**)&w1tL,  g_W1tL);
    cudaGetSymbolAddress((void**)&w2tH,  g_W2tH);
    cudaGetSymbolAddress((void**)&w2tL,  g_W2tL);
    cudaGetSymbolAddress((void**)&cbH,   g_cbH);
    cudaGetSymbolAddress((void**)&cbL,   g_cbL);

    // two-pass gather (L2-resident item ranges) + misc prep
    prepA_kernel<<<5120, 128>>>(items, item_embed, codebook, W1, W2);
    prepB_kernel<<<2048, 128>>>(items, item_embed);

    gemm_mma<128, 0><<<dim3(HHID / 64, BB / 128), 256, SMEM_128>>>(
        meanH, meanL, w1tH, w1tL, b1, nullptr, HHID, DD);
    gemm_mma<64, 1><<<dim3(DD / 64, BB / 64), 256, SMEM_64>>>(
        hidH,  hidL,  w2tH, w2tL, b2, out_ue,  DD,  HHID);
    gemm_mma<128, 2><<<dim3(CBK / 64, BB / 128), 256, SMEM_128>>>(
        uH,    uL,    cbH,  cbL,  nullptr, nullptr, CBK, DD);

    epilogue_kernel<<<BB, 128>>>(codebook, item_embed, pos, neg,
                                 out_q, out_pos, out_neg, out_diff);
}

// round 13
// speedup vs baseline: 1.6618x; 1.1769x over previous
#include <cuda_runtime.h>
#include <cuda_bf16.h>
#include <cstdint>

// Problem constants
#define BB    2048     // batch
#define KHIST 200      // history length
#define DD    512      // latent dim
#define HHID  1024     // 2*D
#define CBK   2048     // codebook size
#define BD    (BB*DD)  // 1048576
#define TH    50000    // item-id threshold: pass A < TH, pass B >= TH

// ---------------- scratch (device globals; no allocation allowed) ----------
__device__ float        g_u[BB * DD];
__device__ float        g_cnorm[CBK];
__device__ float        g_cabs[CBK];      // |codebook_j|
__device__ float        g_bsum[BB];
__device__ int          g_count;          // zero-init; self-resetting
__device__ float        g_macc[BB * DD];  // fp32 partial mean accumulator (pass A)
__device__ int          g_mcnt[BB];       // partial counts (pass A)

// bf16 hi/lo split operands
__device__ __nv_bfloat16 g_meanH[BB * DD],   g_meanL[BB * DD];
__device__ __nv_bfloat16 g_hidH [BB * HHID], g_hidL [BB * HHID];
__device__ __nv_bfloat16 g_W1tH [HHID * DD], g_W1tL [HHID * DD];
__device__ __nv_bfloat16 g_W2tH [DD * HHID], g_W2tL [DD * HHID];

// ---------------------------------------------------------------------------
// Portable PTX helpers (sm_80+; ptxas targets plain sm_103 — no tcgen05)
// ---------------------------------------------------------------------------
__device__ __forceinline__ uint32_t smem_u32(const void* p) {
    uint32_t a;
    asm("{ .reg .u64 t; cvta.to.shared.u64 t, %1; cvt.u32.u64 %0, t; }" : "=r"(a) : "l"(p));
    return a;
}

#define CP_ASYNC16(dst, src) \
    asm volatile("cp.async.cg.shared.global [%0], [%1], 16;" :: "r"(dst), "l"(src))
#define CP_COMMIT() asm volatile("cp.async.commit_group;" ::: "memory")
#define CP_WAIT0()  asm volatile("cp.async.wait_group 0;" ::: "memory")
#define CP_WAIT1()  asm volatile("cp.async.wait_group 1;" ::: "memory")

__device__ __forceinline__ void ldsm4(uint32_t (&r)[4], uint32_t addr) {
    asm volatile("ldmatrix.sync.aligned.m8n8.x4.shared.b16 {%0,%1,%2,%3}, [%4];"
                 : "=r"(r[0]), "=r"(r[1]), "=r"(r[2]), "=r"(r[3]) : "r"(addr));
}

__device__ __forceinline__ void mma16816(float (&d)[4], const uint32_t (&a)[4],
                                         uint32_t b0, uint32_t b1) {
    asm volatile(
        "mma.sync.aligned.m16n8k16.row.col.f32.bf16.bf16.f32 "
        "{%0,%1,%2,%3}, {%4,%5,%6,%7}, {%8,%9}, {%0,%1,%2,%3};"
        : "+f"(d[0]), "+f"(d[1]), "+f"(d[2]), "+f"(d[3])
        : "r"(a[0]), "r"(a[1]), "r"(a[2]), "r"(a[3]), "r"(b0), "r"(b1));
}

__device__ __forceinline__ void split_bf16(float v, __nv_bfloat16& h, __nv_bfloat16& l) {
    h = __float2bfloat16(v);
    l = __float2bfloat16(v - __bfloat162float(h));
}

// ---------------------------------------------------------------------------
// PREP pass A (5120 blocks x 128 thr):
//   blocks [0,2048)    : gather items in (0, TH) -> fp32 partial acc + count
//   blocks [2048,4096) : codebook norms + |c|
//   blocks [4096,4608) : W1^T hi/lo split
//   blocks [4608,5120) : W2^T hi/lo split
// ---------------------------------------------------------------------------
__global__ void __launch_bounds__(128) prepA_kernel(
    const int* __restrict__ items, const float* __restrict__ item_embed,
    const float* __restrict__ codebook,
    const float* __restrict__ W1, const float* __restrict__ W2)
{
    __shared__ int   sidx[KHIST];
    __shared__ float ts[32][33];
    __shared__ float red[4];

    const int blk = blockIdx.x;
    const int t = threadIdx.x;

    if (blk < 2048) {
        int b = blk;
        for (int i = t; i < KHIST; i += 128) sidx[i] = items[b * KHIST + i];
        __syncthreads();
        const float4* E4 = (const float4*)item_embed;
        float4 acc = make_float4(0.f, 0.f, 0.f, 0.f);
        int cnt = 0;
        #pragma unroll 4
        for (int k = 0; k < KHIST; k++) {
            int idx = sidx[k];
            if (idx != 0 && idx < TH) {       // uniform across the block
                float4 v = E4[(size_t)idx * 128 + t];
                acc.x += v.x; acc.y += v.y; acc.z += v.z; acc.w += v.w;
                cnt++;
            }
        }
        ((float4*)g_macc)[(size_t)b * 128 + t] = acc;
        if (t == 0) g_mcnt[b] = cnt;
    } else if (blk < 4096) {
        int j = blk - 2048;
        float4 v = ((const float4*)codebook)[j * 128 + t];
        float s = v.x * v.x + v.y * v.y + v.z * v.z + v.w * v.w;
        #pragma unroll
        for (int o = 16; o > 0; o >>= 1) s += __shfl_down_sync(0xffffffffu, s, o);
        if ((t & 31) == 0) red[t >> 5] = s;
        __syncthreads();
        if (t == 0) {
            float cn = red[0] + red[1] + red[2] + red[3];
            g_cnorm[j] = cn;
            g_cabs[j]  = sqrtf(cn);
        }
    } else {
        const float* W;
        __nv_bfloat16 *WtH, *WtL;
        int KD, ND, w;
        if (blk < 4608) {
            w = blk - 4096; W = W1; WtH = g_W1tH; WtL = g_W1tL; KD = DD; ND = HHID;
        } else {
            w = blk - 4608; W = W2; WtH = g_W2tH; WtL = g_W2tL; KD = HHID; ND = DD;
        }
        int nblk = ND / 32;
        int n0 = (w % nblk) * 32, k0 = (w / nblk) * 32;
        int tx = t & 31, ty = t >> 5;
        #pragma unroll
        for (int i = ty; i < 32; i += 4)
            ts[i][tx] = W[(size_t)(k0 + i) * ND + n0 + tx];
        __syncthreads();
        #pragma unroll
        for (int i = ty; i < 32; i += 4) {
            float v = ts[tx][i];
            __nv_bfloat16 h, l;
            split_bf16(v, h, l);
            size_t o = (size_t)(n0 + i) * KD + k0 + tx;
            WtH[o] = h;
            WtL[o] = l;
        }
    }
}

// ---------------------------------------------------------------------------
// PREP pass B (2048 blocks x 128 thr): gather items >= TH, combine with
// pass-A partials, finalize mean, bf16 hi/lo split.
// ---------------------------------------------------------------------------
__global__ void __launch_bounds__(128) prepB_kernel(
    const int* __restrict__ items, const float* __restrict__ item_embed)
{
    __shared__ int sidx[KHIST];
    const int b = blockIdx.x;
    const int t = threadIdx.x;
    for (int i = t; i < KHIST; i += 128) sidx[i] = items[b * KHIST + i];
    __syncthreads();

    const float4* E4 = (const float4*)item_embed;
    float4 acc = ((const float4*)g_macc)[(size_t)b * 128 + t];
    int cnt = g_mcnt[b];
    #pragma unroll 4
    for (int k = 0; k < KHIST; k++) {
        int idx = sidx[k];
        if (idx >= TH) {                      // uniform across the block
            float4 v = E4[(size_t)idx * 128 + t];
            acc.x += v.x; acc.y += v.y; acc.z += v.z; acc.w += v.w;
            cnt++;
        }
    }
    float inv = 1.0f / (float)cnt;
    float vals[4] = {acc.x * inv, acc.y * inv, acc.z * inv, acc.w * inv};
    size_t base = (size_t)b * DD + t * 4;
    __nv_bfloat16 h[4], l[4];
    #pragma unroll
    for (int i = 0; i < 4; i++) split_bf16(vals[i], h[i], l[i]);
    *(__nv_bfloat162*)&g_meanH[base]     = {h[0], h[1]};
    *(__nv_bfloat162*)&g_meanH[base + 2] = {h[2], h[3]};
    *(__nv_bfloat162*)&g_meanL[base]     = {l[0], l[1]};
    *(__nv_bfloat162*)&g_meanL[base + 2] = {l[2], l[3]};
}

// ---------------------------------------------------------------------------
// Tensor-core GEMM (mma.sync bf16x3, fp32 accum): C = A[M,Kd] @ B[N,Kd]^T
// WHICH=0: hid = relu(mean @ W1t^T + b1)  BM=128
// WHICH=1: u   = hid @ W2t^T + b2         BM=64   (g_u + out_ue only)
// ---------------------------------------------------------------------------
template<int BM, int WHICH>
__global__ void __launch_bounds__(256, (BM == 64) ? 3 : 2) gemm_mma(
    const __nv_bfloat16* __restrict__ Ah, const __nv_bfloat16* __restrict__ Al,
    const __nv_bfloat16* __restrict__ Bh, const __nv_bfloat16* __restrict__ Bl,
    const float* __restrict__ bias, float* __restrict__ out_ue,
    int N, int Kd)
{
    constexpr int BN  = 64;
    constexpr int WM  = BM / 4;
    constexpr int MT  = WM / 16;
    constexpr int STAGE = 2 * (BM + BN) * 128;

    extern __shared__ char smem[];
    const uint32_t sbase = smem_u32(smem);
    const int tid  = threadIdx.x;
    const int lane = tid & 31;
    const int w    = tid >> 5;
    const int warp_m0 = (w >> 1) * WM;
    const int warp_n0 = (w & 1) * 32;
    const int bm = blockIdx.y * BM, bn = blockIdx.x * BN;

    auto loadT = [&](const __nv_bfloat16* __restrict__ src, int row0, int k0,
                     uint32_t dst, int R) {
        #pragma unroll 4
        for (int i = 0; i < R * 8; i += 256) {
            int u = tid + i;
            int r = u >> 3, c8 = u & 7;
            uint32_t sd = dst + r * 128 + ((c8 * 16) ^ ((r & 7) << 4));
            const __nv_bfloat16* gs = src + (size_t)(row0 + r) * Kd + k0 + c8 * 8;
            CP_ASYNC16(sd, gs);
        }
    };
    auto issue = [&](int c, int buf) {
        uint32_t sb = sbase + (uint32_t)buf * STAGE;
        int k0 = c * 64;
        loadT(Ah, bm, k0, sb, BM);
        loadT(Al, bm, k0, sb + BM * 128, BM);
        loadT(Bh, bn, k0, sb + 2 * BM * 128, BN);
        loadT(Bl, bn, k0, sb + 2 * BM * 128 + BN * 128, BN);
    };

    const int tile = lane >> 3, lr = lane & 7;
    const uint32_t xorp = (uint32_t)(lr << 4);
    const int aRow = warp_m0 + ((tile & 1) << 3) + lr;
    const uint32_t aK = (uint32_t)((tile >> 1) << 4);
    const int bRow = warp_n0 + ((tile >> 1) << 3) + lr;
    const uint32_t bK = (uint32_t)((tile & 1) << 4);

    float acc[MT][4][4] = {};

    const int NC = Kd / 64;
    issue(0, 0); CP_COMMIT();
    issue(1, 1); CP_COMMIT();
    CP_WAIT1();
    __syncthreads();

    for (int c = 0; c < NC; c++) {
        uint32_t s0 = sbase + (uint32_t)(c & 1) * STAGE;
        uint32_t pA[2] = { s0, s0 + BM * 128 };
        uint32_t pB[2] = { s0 + 2 * BM * 128, s0 + 2 * BM * 128 + BN * 128 };

        #pragma unroll
        for (int kk = 0; kk < 4; kk++) {
            uint32_t akb = (((uint32_t)kk << 5) + aK) ^ xorp;
            uint32_t bkb = (((uint32_t)kk << 5) + bK) ^ xorp;
            uint32_t a[2][MT][4];
            uint32_t b[2][4][2];
            #pragma unroll
            for (int s = 0; s < 2; s++)
                #pragma unroll
                for (int mt = 0; mt < MT; mt++)
                    ldsm4(a[s][mt], pA[s] + (uint32_t)(aRow + mt * 16) * 128 + akb);
            #pragma unroll
            for (int s = 0; s < 2; s++)
                #pragma unroll
                for (int ng = 0; ng < 2; ng++) {
                    uint32_t t4[4];
                    ldsm4(t4, pB[s] + (uint32_t)(bRow + ng * 16) * 128 + bkb);
                    b[s][2 * ng][0] = t4[0]; b[s][2 * ng][1] = t4[1];
                    b[s][2 * ng + 1][0] = t4[2]; b[s][2 * ng + 1][1] = t4[3];
                }
            #pragma unroll
            for (int mt = 0; mt < MT; mt++)
                #pragma unroll
                for (int nt = 0; nt < 4; nt++)
                    mma16816(acc[mt][nt], a[0][mt], b[0][nt][0], b[0][nt][1]);
            #pragma unroll
            for (int mt = 0; mt < MT; mt++)
                #pragma unroll
                for (int nt = 0; nt < 4; nt++)
                    mma16816(acc[mt][nt], a[0][mt], b[1][nt][0], b[1][nt][1]);
            #pragma unroll
            for (int mt = 0; mt < MT; mt++)
                #pragma unroll
                for (int nt = 0; nt < 4; nt++)
                    mma16816(acc[mt][nt], a[1][mt], b[0][nt][0], b[0][nt][1]);
        }

        if (c == NC - 1) break;
        __syncthreads();
        if (c + 2 < NC) { issue(c + 2, c & 1); CP_COMMIT(); CP_WAIT1(); }
        else            { CP_WAIT0(); }
        __syncthreads();
    }

    const int lr4 = lane >> 2;
    const int lc2 = (lane & 3) * 2;

    #pragma unroll
    for (int mt = 0; mt < MT; mt++)
        #pragma unroll
        for (int half = 0; half < 2; half++) {
            int row = bm + warp_m0 + mt * 16 + lr4 + half * 8;
            #pragma unroll
            for (int nt = 0; nt < 4; nt++) {
                int col = bn + warp_n0 + nt * 8 + lc2;
                float2 bv = *(const float2*)&bias[col];
                float v0 = acc[mt][nt][half * 2 + 0] + bv.x;
                float v1 = acc[mt][nt][half * 2 + 1] + bv.y;
                size_t o = (size_t)row * N + col;
                if (WHICH == 0) {
                    v0 = fmaxf(v0, 0.f); v1 = fmaxf(v1, 0.f);
                    __nv_bfloat16 h0, l0, h1, l1;
                    split_bf16(v0, h0, l0); split_bf16(v1, h1, l1);
                    *(__nv_bfloat162*)&g_hidH[o] = {h0, h1};
                    *(__nv_bfloat162*)&g_hidL[o] = {l0, l1};
                } else {
                    *(float2*)&g_u[o] = make_float2(v0, v1);
                    out_ue[o] = v0; out_ue[o + 1] = v1;
                }
            }
        }
}

// ---------------------------------------------------------------------------
// Fused VQ + epilogue (2048 blocks x 128 thr). Per batch row:
//   1. |u| from g_u; bound scan over (cnorm, |c|) table: candidates with
//      cnorm_j - 2|u||c_j| <= min_k(cnorm_k + 2|u||c_k|) + margin.
//      (Cauchy-Schwarz => true argmin of cnorm_j - 2 u.c_j is always kept.)
//   2. exact fp32 dot for each candidate; argmin, ties -> smaller j.
//   3. q/quant/pos/neg outputs + diff partial; last block reduces diff.
// ---------------------------------------------------------------------------
__global__ void __launch_bounds__(128) vq_epilogue_kernel(
    const float* __restrict__ codebook, const float* __restrict__ item_embed,
    const int* __restrict__ pos, const int* __restrict__ neg,
    float* __restrict__ out_q, float* __restrict__ out_pos,
    float* __restrict__ out_neg, float* __restrict__ out_diff)
{
    __shared__ float su[DD];          // u row (2 KB)
    __shared__ int   cand[CBK];       // candidate list (8 KB; worst case all)
    __shared__ float red[4];
    __shared__ float s_bcast;
    __shared__ int   s_cnt;
    __shared__ bool  s_last;

    const int b = blockIdx.x;
    const int t = threadIdx.x;

    // load u row; compute |u|
    float4 u4 = ((const float4*)g_u)[(size_t)b * 128 + t];
    ((float4*)su)[t] = u4;
    float p = u4.x * u4.x + u4.y * u4.y + u4.z * u4.z + u4.w * u4.w;
    #pragma unroll
    for (int o = 16; o > 0; o >>= 1) p += __shfl_down_sync(0xffffffffu, p, o);
    if ((t & 31) == 0) red[t >> 5] = p;
    if (t == 0) s_cnt = 0;
    __syncthreads();
    const float tu = 2.0f * sqrtf(red[0] + red[1] + red[2] + red[3]);

    // pass 1: U = min_j (cnorm_j + tu*|c_j|)
    float locU = 3.0e38f;
    for (int j = t; j < CBK; j += 128)
        locU = fminf(locU, fmaf(tu, g_cabs[j], g_cnorm[j]));
    #pragma unroll
    for (int o = 16; o > 0; o >>= 1)
        locU = fminf(locU, __shfl_down_sync(0xffffffffu, locU, o));
    if ((t & 31) == 0) red[t >> 5] = locU;
    __syncthreads();
    const float U = fminf(fminf(red[0], red[1]), fminf(red[2], red[3])) + 1e-2f;

    // pass 2: collect candidates with lower bound <= U
    for (int j = t; j < CBK; j += 128)
        if (fmaf(-tu, g_cabs[j], g_cnorm[j]) <= U)
            cand[atomicAdd(&s_cnt, 1)] = j;
    __syncthreads();
    const int ncand = s_cnt;

    // exact fp32 scores for candidates; argmin with smaller-j tie-break
    float best = 3.0e38f;
    int   bid  = 0x7fffffff;
    for (int i = 0; i < ncand; i++) {
        int j = cand[i];
        float4 c4 = ((const float4*)codebook)[(size_t)j * 128 + t];
        float4 uu = ((const float4*)su)[t];
        float d = c4.x * uu.x + c4.y * uu.y + c4.z * uu.z + c4.w * uu.w;
        #pragma unroll
        for (int o = 16; o > 0; o >>= 1) d += __shfl_down_sync(0xffffffffu, d, o);
        __syncthreads();               // protect red[] reuse
        if ((t & 31) == 0) red[t >> 5] = d;
        __syncthreads();
        if (t == 0) s_bcast = red[0] + red[1] + red[2] + red[3];
        __syncthreads();
        float s = g_cnorm[j] - 2.0f * s_bcast;
        if (s < best || (s == best && j < bid)) { best = s; bid = j; }
    }
    const int id = bid;

    // outputs
    float4 q = ((const float4*)codebook)[(size_t)id * 128 + t];
    float4 u = ((const float4*)su)[t];
    float4 d = make_float4(q.x - u.x, q.y - u.y, q.z - u.z, q.w - u.w);
    float4 qu = make_float4(u.x + d.x, u.y + d.y, u.z + d.z, u.w + d.w);
    ((float4*)out_q)[(size_t)b * 128 + t] = qu;

    int pp = pos[b], nn = neg[b];
    ((float4*)out_pos)[(size_t)b * 128 + t] = ((const float4*)item_embed)[(size_t)pp * 128 + t];
    ((float4*)out_neg)[(size_t)b * 128 + t] = ((const float4*)item_embed)[(size_t)nn * 128 + t];

    float ds = d.x * d.x + d.y * d.y + d.z * d.z + d.w * d.w;
    #pragma unroll
    for (int o = 16; o > 0; o >>= 1) ds += __shfl_down_sync(0xffffffffu, ds, o);
    __syncthreads();
    if ((t & 31) == 0) red[t >> 5] = ds;
    __syncthreads();
    if (t == 0) {
        g_bsum[b] = red[0] + red[1] + red[2] + red[3];
        __threadfence();
        int c = atomicAdd(&g_count, 1);
        s_last = (c == BB - 1);
    }
    __syncthreads();

    if (s_last) {
        __threadfence();
        float s = 0.f;
        #pragma unroll
        for (int i = 0; i < BB / 128; i++) s += g_bsum[t + i * 128];
        __shared__ float sv[128];
        sv[t] = s;
        __syncthreads();
        for (int o = 64; o > 0; o >>= 1) {
            if (t < o) sv[t] += sv[t + o];
            __syncthreads();
        }
        if (t == 0) {
            *out_diff = sv[0] * (1.0f / (float)BD);
            g_count = 0;                       // reset for next graph replay
        }
    }
}

// ---------------------------------------------------------------------------
extern "C" void kernel_launch(void* const* d_in, const int* in_sizes, int n_in,
                              void* d_out, int out_size)
{
    const int*   items      = (const int*)  d_in[1];
    const int*   pos        = (const int*)  d_in[2];
    const int*   neg        = (const int*)  d_in[3];
    const float* item_embed = (const float*)d_in[4];
    const float* W1         = (const float*)d_in[5];
    const float* b1         = (const float*)d_in[6];
    const float* W2         = (const float*)d_in[7];
    const float* b2         = (const float*)d_in[8];
    const float* codebook   = (const float*)d_in[9];

    float* out      = (float*)d_out;
    float* out_q    = out;
    float* out_pos  = out + (size_t)BD;
    float* out_neg  = out + (size_t)2 * BD;
    float* out_diff = out + (size_t)3 * BD;
    float* out_ue   = out + (size_t)3 * BD + 1;

    const int SMEM_128 = 2 * 2 * (128 + 64) * 128;  // 98304
    const int SMEM_64  = 2 * 2 * (64 + 64) * 128;   // 65536
    cudaFuncSetAttribute((const void*)gemm_mma<128, 0>,
                         cudaFuncAttributeMaxDynamicSharedMemorySize, SMEM_128);
    cudaFuncSetAttribute((const void*)gemm_mma<64, 1>,
                         cudaFuncAttributeMaxDynamicSharedMemorySize, SMEM_64);

    __nv_bfloat16 *meanH, *meanL, *hidH, *hidL, *w1tH, *w1tL, *w2tH, *w2tL;
    cudaGetSymbolAddress((void**)&meanH, g_meanH);
    cudaGetSymbolAddress((void**)&meanL, g_meanL);
    cudaGetSymbolAddress((void**)&hidH,  g_hidH);
    cudaGetSymbolAddress((void**)&hidL,  g_hidL);
    cudaGetSymbolAddress((void**)&w1tH,  g_W1tH);
    cudaGetSymbolAddress((void**)&w1tL,  g_W1tL);
    cudaGetSymbolAddress((void**)&w2tH,  g_W2tH);
    cudaGetSymbolAddress((void**)&w2tL,  g_W2tL);

    // two-pass gather (L2-resident item ranges) + misc prep
    prepA_kernel<<<5120, 128>>>(items, item_embed, codebook, W1, W2);
    prepB_kernel<<<2048, 128>>>(items, item_embed);

    gemm_mma<128, 0><<<dim3(HHID / 64, BB / 128), 256, SMEM_128>>>(
        meanH, meanL, w1tH, w1tL, b1, nullptr, HHID, DD);
    gemm_mma<64, 1><<<dim3(DD / 64, BB / 64), 256, SMEM_64>>>(
        hidH,  hidL,  w2tH, w2tL, b2, out_ue,  DD,  HHID);

    vq_epilogue_kernel<<<BB, 128>>>(codebook, item_embed, pos, neg,
                                    out_q, out_pos, out_neg, out_diff);
}

// round 14
// speedup vs baseline: 1.7030x; 1.0248x over previous
#include <cuda_runtime.h>
#include <cuda_bf16.h>
#include <cstdint>

// Problem constants
#define BB    2048     // batch
#define KHIST 200      // history length
#define DD    512      // latent dim
#define HHID  1024     // 2*D
#define CBK   2048     // codebook size
#define BD    (BB*DD)  // 1048576
#define TH    50000    // item-id threshold: pass A < TH, pass B >= TH

// ---------------- scratch (device globals; no allocation allowed) ----------
__device__ float        g_u[BB * DD];
__device__ float2       g_cn2[CBK];       // (cnorm_j, |c_j|)
__device__ float        g_bsum[BB];
__device__ int          g_count;          // zero-init; self-resetting
__device__ float        g_macc[BB * DD];  // fp32 partial mean accumulator (pass A)
__device__ int          g_mcnt[BB];       // partial counts (pass A)

// bf16 hi/lo split operands
__device__ __nv_bfloat16 g_meanH[BB * DD],   g_meanL[BB * DD];
__device__ __nv_bfloat16 g_hidH [BB * HHID], g_hidL [BB * HHID];
__device__ __nv_bfloat16 g_W1tH [HHID * DD], g_W1tL [HHID * DD];
__device__ __nv_bfloat16 g_W2tH [DD * HHID], g_W2tL [DD * HHID];

// ---------------------------------------------------------------------------
// Portable PTX helpers (sm_80+; ptxas targets plain sm_103 — no tcgen05)
// ---------------------------------------------------------------------------
__device__ __forceinline__ uint32_t smem_u32(const void* p) {
    uint32_t a;
    asm("{ .reg .u64 t; cvta.to.shared.u64 t, %1; cvt.u32.u64 %0, t; }" : "=r"(a) : "l"(p));
    return a;
}

#define CP_ASYNC16(dst, src) \
    asm volatile("cp.async.cg.shared.global [%0], [%1], 16;" :: "r"(dst), "l"(src))
#define CP_COMMIT() asm volatile("cp.async.commit_group;" ::: "memory")
#define CP_WAIT0()  asm volatile("cp.async.wait_group 0;" ::: "memory")
#define CP_WAIT1()  asm volatile("cp.async.wait_group 1;" ::: "memory")

__device__ __forceinline__ void ldsm4(uint32_t (&r)[4], uint32_t addr) {
    asm volatile("ldmatrix.sync.aligned.m8n8.x4.shared.b16 {%0,%1,%2,%3}, [%4];"
                 : "=r"(r[0]), "=r"(r[1]), "=r"(r[2]), "=r"(r[3]) : "r"(addr));
}

__device__ __forceinline__ void mma16816(float (&d)[4], const uint32_t (&a)[4],
                                         uint32_t b0, uint32_t b1) {
    asm volatile(
        "mma.sync.aligned.m16n8k16.row.col.f32.bf16.bf16.f32 "
        "{%0,%1,%2,%3}, {%4,%5,%6,%7}, {%8,%9}, {%0,%1,%2,%3};"
        : "+f"(d[0]), "+f"(d[1]), "+f"(d[2]), "+f"(d[3])
        : "r"(a[0]), "r"(a[1]), "r"(a[2]), "r"(a[3]), "r"(b0), "r"(b1));
}

__device__ __forceinline__ void split_bf16(float v, __nv_bfloat16& h, __nv_bfloat16& l) {
    h = __float2bfloat16(v);
    l = __float2bfloat16(v - __bfloat162float(h));
}

// ---------------------------------------------------------------------------
// PREP pass A (5120 blocks x 128 thr):
//   blocks [0,2048)    : gather items in (0, TH) -> fp32 partial acc + count
//   blocks [2048,4096) : codebook norms -> (cnorm, |c|)
//   blocks [4096,4608) : W1^T hi/lo split
//   blocks [4608,5120) : W2^T hi/lo split
// ---------------------------------------------------------------------------
__global__ void __launch_bounds__(128) prepA_kernel(
    const int* __restrict__ items, const float* __restrict__ item_embed,
    const float* __restrict__ codebook,
    const float* __restrict__ W1, const float* __restrict__ W2)
{
    __shared__ int   sidx[KHIST];
    __shared__ float ts[32][33];
    __shared__ float red[4];

    const int blk = blockIdx.x;
    const int t = threadIdx.x;

    if (blk < 2048) {
        int b = blk;
        for (int i = t; i < KHIST; i += 128) sidx[i] = items[b * KHIST + i];
        __syncthreads();
        const float4* E4 = (const float4*)item_embed;
        float4 acc = make_float4(0.f, 0.f, 0.f, 0.f);
        int cnt = 0;
        #pragma unroll 4
        for (int k = 0; k < KHIST; k++) {
            int idx = sidx[k];
            if (idx != 0 && idx < TH) {       // uniform across the block
                float4 v = E4[(size_t)idx * 128 + t];
                acc.x += v.x; acc.y += v.y; acc.z += v.z; acc.w += v.w;
                cnt++;
            }
        }
        ((float4*)g_macc)[(size_t)b * 128 + t] = acc;
        if (t == 0) g_mcnt[b] = cnt;
    } else if (blk < 4096) {
        int j = blk - 2048;
        float4 v = ((const float4*)codebook)[j * 128 + t];
        float s = v.x * v.x + v.y * v.y + v.z * v.z + v.w * v.w;
        #pragma unroll
        for (int o = 16; o > 0; o >>= 1) s += __shfl_down_sync(0xffffffffu, s, o);
        if ((t & 31) == 0) red[t >> 5] = s;
        __syncthreads();
        if (t == 0) {
            float cn = red[0] + red[1] + red[2] + red[3];
            g_cn2[j] = make_float2(cn, sqrtf(cn));
        }
    } else {
        const float* W;
        __nv_bfloat16 *WtH, *WtL;
        int KD, ND, w;
        if (blk < 4608) {
            w = blk - 4096; W = W1; WtH = g_W1tH; WtL = g_W1tL; KD = DD; ND = HHID;
        } else {
            w = blk - 4608; W = W2; WtH = g_W2tH; WtL = g_W2tL; KD = HHID; ND = DD;
        }
        int nblk = ND / 32;
        int n0 = (w % nblk) * 32, k0 = (w / nblk) * 32;
        int tx = t & 31, ty = t >> 5;
        #pragma unroll
        for (int i = ty; i < 32; i += 4)
            ts[i][tx] = W[(size_t)(k0 + i) * ND + n0 + tx];
        __syncthreads();
        #pragma unroll
        for (int i = ty; i < 32; i += 4) {
            float v = ts[tx][i];
            __nv_bfloat16 h, l;
            split_bf16(v, h, l);
            size_t o = (size_t)(n0 + i) * KD + k0 + tx;
            WtH[o] = h;
            WtL[o] = l;
        }
    }
}

// ---------------------------------------------------------------------------
// PREP pass B (2048 blocks x 128 thr): gather items >= TH, combine with
// pass-A partials, finalize mean, bf16 hi/lo split.
// ---------------------------------------------------------------------------
__global__ void __launch_bounds__(128) prepB_kernel(
    const int* __restrict__ items, const float* __restrict__ item_embed)
{
    __shared__ int sidx[KHIST];
    const int b = blockIdx.x;
    const int t = threadIdx.x;
    for (int i = t; i < KHIST; i += 128) sidx[i] = items[b * KHIST + i];
    __syncthreads();

    const float4* E4 = (const float4*)item_embed;
    float4 acc = ((const float4*)g_macc)[(size_t)b * 128 + t];
    int cnt = g_mcnt[b];
    #pragma unroll 4
    for (int k = 0; k < KHIST; k++) {
        int idx = sidx[k];
        if (idx >= TH) {                      // uniform across the block
            float4 v = E4[(size_t)idx * 128 + t];
            acc.x += v.x; acc.y += v.y; acc.z += v.z; acc.w += v.w;
            cnt++;
        }
    }
    float inv = 1.0f / (float)cnt;
    float vals[4] = {acc.x * inv, acc.y * inv, acc.z * inv, acc.w * inv};
    size_t base = (size_t)b * DD + t * 4;
    __nv_bfloat16 h[4], l[4];
    #pragma unroll
    for (int i = 0; i < 4; i++) split_bf16(vals[i], h[i], l[i]);
    *(__nv_bfloat162*)&g_meanH[base]     = {h[0], h[1]};
    *(__nv_bfloat162*)&g_meanH[base + 2] = {h[2], h[3]};
    *(__nv_bfloat162*)&g_meanL[base]     = {l[0], l[1]};
    *(__nv_bfloat162*)&g_meanL[base + 2] = {l[2], l[3]};
}

// ---------------------------------------------------------------------------
// Tensor-core GEMM (mma.sync bf16x3, fp32 accum): C = A[M,Kd] @ B[N,Kd]^T
// WHICH=0: hid = relu(mean @ W1t^T + b1)  BM=128, grid(16,16)
// WHICH=1: u   = hid @ W2t^T + b2         BM=128, grid(8,16) = one full wave
// ---------------------------------------------------------------------------
template<int BM, int WHICH>
__global__ void __launch_bounds__(256, (BM == 64) ? 3 : 2) gemm_mma(
    const __nv_bfloat16* __restrict__ Ah, const __nv_bfloat16* __restrict__ Al,
    const __nv_bfloat16* __restrict__ Bh, const __nv_bfloat16* __restrict__ Bl,
    const float* __restrict__ bias, float* __restrict__ out_ue,
    int N, int Kd)
{
    constexpr int BN  = 64;
    constexpr int WM  = BM / 4;
    constexpr int MT  = WM / 16;
    constexpr int STAGE = 2 * (BM + BN) * 128;

    extern __shared__ char smem[];
    const uint32_t sbase = smem_u32(smem);
    const int tid  = threadIdx.x;
    const int lane = tid & 31;
    const int w    = tid >> 5;
    const int warp_m0 = (w >> 1) * WM;
    const int warp_n0 = (w & 1) * 32;
    const int bm = blockIdx.y * BM, bn = blockIdx.x * BN;

    auto loadT = [&](const __nv_bfloat16* __restrict__ src, int row0, int k0,
                     uint32_t dst, int R) {
        #pragma unroll 4
        for (int i = 0; i < R * 8; i += 256) {
            int u = tid + i;
            int r = u >> 3, c8 = u & 7;
            uint32_t sd = dst + r * 128 + ((c8 * 16) ^ ((r & 7) << 4));
            const __nv_bfloat16* gs = src + (size_t)(row0 + r) * Kd + k0 + c8 * 8;
            CP_ASYNC16(sd, gs);
        }
    };
    auto issue = [&](int c, int buf) {
        uint32_t sb = sbase + (uint32_t)buf * STAGE;
        int k0 = c * 64;
        loadT(Ah, bm, k0, sb, BM);
        loadT(Al, bm, k0, sb + BM * 128, BM);
        loadT(Bh, bn, k0, sb + 2 * BM * 128, BN);
        loadT(Bl, bn, k0, sb + 2 * BM * 128 + BN * 128, BN);
    };

    const int tile = lane >> 3, lr = lane & 7;
    const uint32_t xorp = (uint32_t)(lr << 4);
    const int aRow = warp_m0 + ((tile & 1) << 3) + lr;
    const uint32_t aK = (uint32_t)((tile >> 1) << 4);
    const int bRow = warp_n0 + ((tile >> 1) << 3) + lr;
    const uint32_t bK = (uint32_t)((tile & 1) << 4);

    float acc[MT][4][4] = {};

    const int NC = Kd / 64;
    issue(0, 0); CP_COMMIT();
    issue(1, 1); CP_COMMIT();
    CP_WAIT1();
    __syncthreads();

    for (int c = 0; c < NC; c++) {
        uint32_t s0 = sbase + (uint32_t)(c & 1) * STAGE;
        uint32_t pA[2] = { s0, s0 + BM * 128 };
        uint32_t pB[2] = { s0 + 2 * BM * 128, s0 + 2 * BM * 128 + BN * 128 };

        #pragma unroll
        for (int kk = 0; kk < 4; kk++) {
            uint32_t akb = (((uint32_t)kk << 5) + aK) ^ xorp;
            uint32_t bkb = (((uint32_t)kk << 5) + bK) ^ xorp;
            uint32_t a[2][MT][4];
            uint32_t b[2][4][2];
            #pragma unroll
            for (int s = 0; s < 2; s++)
                #pragma unroll
                for (int mt = 0; mt < MT; mt++)
                    ldsm4(a[s][mt], pA[s] + (uint32_t)(aRow + mt * 16) * 128 + akb);
            #pragma unroll
            for (int s = 0; s < 2; s++)
                #pragma unroll
                for (int ng = 0; ng < 2; ng++) {
                    uint32_t t4[4];
                    ldsm4(t4, pB[s] + (uint32_t)(bRow + ng * 16) * 128 + bkb);
                    b[s][2 * ng][0] = t4[0]; b[s][2 * ng][1] = t4[1];
                    b[s][2 * ng + 1][0] = t4[2]; b[s][2 * ng + 1][1] = t4[3];
                }
            #pragma unroll
            for (int mt = 0; mt < MT; mt++)
                #pragma unroll
                for (int nt = 0; nt < 4; nt++)
                    mma16816(acc[mt][nt], a[0][mt], b[0][nt][0], b[0][nt][1]);
            #pragma unroll
            for (int mt = 0; mt < MT; mt++)
                #pragma unroll
                for (int nt = 0; nt < 4; nt++)
                    mma16816(acc[mt][nt], a[0][mt], b[1][nt][0], b[1][nt][1]);
            #pragma unroll
            for (int mt = 0; mt < MT; mt++)
                #pragma unroll
                for (int nt = 0; nt < 4; nt++)
                    mma16816(acc[mt][nt], a[1][mt], b[0][nt][0], b[0][nt][1]);
        }

        if (c == NC - 1) break;
        __syncthreads();
        if (c + 2 < NC) { issue(c + 2, c & 1); CP_COMMIT(); CP_WAIT1(); }
        else            { CP_WAIT0(); }
        __syncthreads();
    }

    const int lr4 = lane >> 2;
    const int lc2 = (lane & 3) * 2;

    #pragma unroll
    for (int mt = 0; mt < MT; mt++)
        #pragma unroll
        for (int half = 0; half < 2; half++) {
            int row = bm + warp_m0 + mt * 16 + lr4 + half * 8;
            #pragma unroll
            for (int nt = 0; nt < 4; nt++) {
                int col = bn + warp_n0 + nt * 8 + lc2;
                float2 bv = *(const float2*)&bias[col];
                float v0 = acc[mt][nt][half * 2 + 0] + bv.x;
                float v1 = acc[mt][nt][half * 2 + 1] + bv.y;
                size_t o = (size_t)row * N + col;
                if (WHICH == 0) {
                    v0 = fmaxf(v0, 0.f); v1 = fmaxf(v1, 0.f);
                    __nv_bfloat16 h0, l0, h1, l1;
                    split_bf16(v0, h0, l0); split_bf16(v1, h1, l1);
                    *(__nv_bfloat162*)&g_hidH[o] = {h0, h1};
                    *(__nv_bfloat162*)&g_hidL[o] = {l0, l1};
                } else {
                    *(float2*)&g_u[o] = make_float2(v0, v1);
                    out_ue[o] = v0; out_ue[o + 1] = v1;
                }
            }
        }
}

// ---------------------------------------------------------------------------
// Fused VQ + epilogue (2048 blocks x 128 thr). Per batch row:
//   1. |u|; bound scan over packed (cnorm,|c|): keep j with
//      cnorm_j - 2|u||c_j| <= min_k(cnorm_k + 2|u||c_k|) + margin.
//      (Cauchy-Schwarz: true argmin always kept.)
//   2. exact fp32 dot per candidate; argmin, ties -> smaller j.
//   3. q/quant/pos/neg outputs + diff partial; last block reduces diff.
// pos/neg item loads issued up front to overlap their latency with the scan.
// ---------------------------------------------------------------------------
__global__ void __launch_bounds__(128) vq_epilogue_kernel(
    const float* __restrict__ codebook, const float* __restrict__ item_embed,
    const int* __restrict__ pos, const int* __restrict__ neg,
    float* __restrict__ out_q, float* __restrict__ out_pos,
    float* __restrict__ out_neg, float* __restrict__ out_diff)
{
    __shared__ float su[DD];          // u row (2 KB)
    __shared__ int   cand[CBK];       // candidate list (8 KB; worst case all)
    __shared__ float red[4];
    __shared__ float s_bcast;
    __shared__ int   s_cnt;
    __shared__ bool  s_last;

    const int b = blockIdx.x;
    const int t = threadIdx.x;

    // issue independent loads early (latency overlaps the scan below)
    const int pp = pos[b], nn = neg[b];
    const float4 pv4 = ((const float4*)item_embed)[(size_t)pp * 128 + t];
    const float4 nv4 = ((const float4*)item_embed)[(size_t)nn * 128 + t];

    // load u row; compute |u|
    float4 u4 = ((const float4*)g_u)[(size_t)b * 128 + t];
    ((float4*)su)[t] = u4;
    float p = u4.x * u4.x + u4.y * u4.y + u4.z * u4.z + u4.w * u4.w;
    #pragma unroll
    for (int o = 16; o > 0; o >>= 1) p += __shfl_down_sync(0xffffffffu, p, o);
    if ((t & 31) == 0) red[t >> 5] = p;
    if (t == 0) s_cnt = 0;
    __syncthreads();
    const float tu = 2.0f * sqrtf(red[0] + red[1] + red[2] + red[3]);

    // pass 1: U = min_j (cnorm_j + tu*|c_j|)
    float locU = 3.0e38f;
    for (int j = t; j < CBK; j += 128) {
        float2 c2 = g_cn2[j];
        locU = fminf(locU, fmaf(tu, c2.y, c2.x));
    }
    #pragma unroll
    for (int o = 16; o > 0; o >>= 1)
        locU = fminf(locU, __shfl_down_sync(0xffffffffu, locU, o));
    if ((t & 31) == 0) red[t >> 5] = locU;
    __syncthreads();
    const float U = fminf(fminf(red[0], red[1]), fminf(red[2], red[3])) + 1e-2f;

    // pass 2: collect candidates with lower bound <= U
    for (int j = t; j < CBK; j += 128) {
        float2 c2 = g_cn2[j];
        if (fmaf(-tu, c2.y, c2.x) <= U)
            cand[atomicAdd(&s_cnt, 1)] = j;
    }
    __syncthreads();
    const int ncand = s_cnt;

    // exact fp32 scores for candidates; argmin with smaller-j tie-break
    float best = 3.0e38f;
    int   bid  = 0x7fffffff;
    for (int i = 0; i < ncand; i++) {
        int j = cand[i];
        float4 c4 = ((const float4*)codebook)[(size_t)j * 128 + t];
        float4 uu = ((const float4*)su)[t];
        float d = c4.x * uu.x + c4.y * uu.y + c4.z * uu.z + c4.w * uu.w;
        #pragma unroll
        for (int o = 16; o > 0; o >>= 1) d += __shfl_down_sync(0xffffffffu, d, o);
        __syncthreads();               // protect red[] reuse
        if ((t & 31) == 0) red[t >> 5] = d;
        __syncthreads();
        if (t == 0) s_bcast = red[0] + red[1] + red[2] + red[3];
        __syncthreads();
        float s = g_cn2[j].x - 2.0f * s_bcast;
        if (s < best || (s == best && j < bid)) { best = s; bid = j; }
    }
    const int id = bid;

    // outputs
    float4 q = ((const float4*)codebook)[(size_t)id * 128 + t];
    float4 u = ((const float4*)su)[t];
    float4 d = make_float4(q.x - u.x, q.y - u.y, q.z - u.z, q.w - u.w);
    float4 qu = make_float4(u.x + d.x, u.y + d.y, u.z + d.z, u.w + d.w);
    ((float4*)out_q)[(size_t)b * 128 + t] = qu;
    ((float4*)out_pos)[(size_t)b * 128 + t] = pv4;
    ((float4*)out_neg)[(size_t)b * 128 + t] = nv4;

    float ds = d.x * d.x + d.y * d.y + d.z * d.z + d.w * d.w;
    #pragma unroll
    for (int o = 16; o > 0; o >>= 1) ds += __shfl_down_sync(0xffffffffu, ds, o);
    __syncthreads();
    if ((t & 31) == 0) red[t >> 5] = ds;
    __syncthreads();
    if (t == 0) {
        g_bsum[b] = red[0] + red[1] + red[2] + red[3];
        __threadfence();
        int c = atomicAdd(&g_count, 1);
        s_last = (c == BB - 1);
    }
    __syncthreads();

    if (s_last) {
        __threadfence();
        float s = 0.f;
        #pragma unroll
        for (int i = 0; i < BB / 128; i++) s += g_bsum[t + i * 128];
        __shared__ float sv[128];
        sv[t] = s;
        __syncthreads();
        for (int o = 64; o > 0; o >>= 1) {
            if (t < o) sv[t] += sv[t + o];
            __syncthreads();
        }
        if (t == 0) {
            *out_diff = sv[0] * (1.0f / (float)BD);
            g_count = 0;                       // reset for next graph replay
        }
    }
}

// ---------------------------------------------------------------------------
extern "C" void kernel_launch(void* const* d_in, const int* in_sizes, int n_in,
                              void* d_out, int out_size)
{
    const int*   items      = (const int*)  d_in[1];
    const int*   pos        = (const int*)  d_in[2];
    const int*   neg        = (const int*)  d_in[3];
    const float* item_embed = (const float*)d_in[4];
    const float* W1         = (const float*)d_in[5];
    const float* b1         = (const float*)d_in[6];
    const float* W2         = (const float*)d_in[7];
    const float* b2         = (const float*)d_in[8];
    const float* codebook   = (const float*)d_in[9];

    float* out      = (float*)d_out;
    float* out_q    = out;
    float* out_pos  = out + (size_t)BD;
    float* out_neg  = out + (size_t)2 * BD;
    float* out_diff = out + (size_t)3 * BD;
    float* out_ue   = out + (size_t)3 * BD + 1;

    const int SMEM_128 = 2 * 2 * (128 + 64) * 128;  // 98304
    cudaFuncSetAttribute((const void*)gemm_mma<128, 0>,
                         cudaFuncAttributeMaxDynamicSharedMemorySize, SMEM_128);
    cudaFuncSetAttribute((const void*)gemm_mma<128, 1>,
                         cudaFuncAttributeMaxDynamicSharedMemorySize, SMEM_128);

    __nv_bfloat16 *meanH, *meanL, *hidH, *hidL, *w1tH, *w1tL, *w2tH, *w2tL;
    cudaGetSymbolAddress((void**)&meanH, g_meanH);
    cudaGetSymbolAddress((void**)&meanL, g_meanL);
    cudaGetSymbolAddress((void**)&hidH,  g_hidH);
    cudaGetSymbolAddress((void**)&hidL,  g_hidL);
    cudaGetSymbolAddress((void**)&w1tH,  g_W1tH);
    cudaGetSymbolAddress((void**)&w1tL,  g_W1tL);
    cudaGetSymbolAddress((void**)&w2tH,  g_W2tH);
    cudaGetSymbolAddress((void**)&w2tL,  g_W2tL);

    // two-pass gather (L2-resident item ranges) + misc prep
    prepA_kernel<<<5120, 128>>>(items, item_embed, codebook, W1, W2);
    prepB_kernel<<<2048, 128>>>(items, item_embed);

    gemm_mma<128, 0><<<dim3(HHID / 64, BB / 128), 256, SMEM_128>>>(
        meanH, meanL, w1tH, w1tL, b1, nullptr, HHID, DD);
    gemm_mma<128, 1><<<dim3(DD / 64, BB / 128), 256, SMEM_128>>>(
        hidH,  hidL,  w2tH, w2tL, b2, out_ue,  DD,  HHID);

    vq_epilogue_kernel<<<BB, 128>>>(codebook, item_embed, pos, neg,
                                    out_q, out_pos, out_neg, out_diff);
}

// round 15
// speedup vs baseline: 1.7091x; 1.0036x over previous
#include <cuda_runtime.h>
#include <cuda_bf16.h>
#include <cstdint>

// Problem constants
#define BB    2048     // batch
#define KHIST 200      // history length
#define DD    512      // latent dim
#define HHID  1024     // 2*D
#define CBK   2048     // codebook size
#define BD    (BB*DD)  // 1048576
#define TH    50000    // item-id threshold: pass A < TH, pass B >= TH

// ---------------- scratch (device globals; no allocation allowed) ----------
__device__ float        g_u[BB * DD];
__device__ float2       g_cn2[CBK];       // (cnorm_j, |c_j|)
__device__ float        g_bsum[BB];
__device__ int          g_count;          // zero-init; self-resetting
__device__ float        g_macc[BB * DD];  // fp32 partial mean accumulator (pass A)
__device__ int          g_mcnt[BB];       // partial counts (pass A)

// bf16 hi/lo split operands
__device__ __nv_bfloat16 g_meanH[BB * DD],   g_meanL[BB * DD];
__device__ __nv_bfloat16 g_hidH [BB * HHID], g_hidL [BB * HHID];
__device__ __nv_bfloat16 g_W1tH [HHID * DD], g_W1tL [HHID * DD];
__device__ __nv_bfloat16 g_W2tH [DD * HHID], g_W2tL [DD * HHID];

// ---------------------------------------------------------------------------
// Portable PTX helpers (sm_80+; ptxas targets plain sm_103 — no tcgen05)
// ---------------------------------------------------------------------------
__device__ __forceinline__ uint32_t smem_u32(const void* p) {
    uint32_t a;
    asm("{ .reg .u64 t; cvta.to.shared.u64 t, %1; cvt.u32.u64 %0, t; }" : "=r"(a) : "l"(p));
    return a;
}

#define CP_ASYNC16(dst, src) \
    asm volatile("cp.async.cg.shared.global [%0], [%1], 16;" :: "r"(dst), "l"(src))
#define CP_COMMIT() asm volatile("cp.async.commit_group;" ::: "memory")

template<int N>
__device__ __forceinline__ void cp_wait() {
    asm volatile("cp.async.wait_group %0;" :: "n"(N) : "memory");
}

__device__ __forceinline__ void ldsm4(uint32_t (&r)[4], uint32_t addr) {
    asm volatile("ldmatrix.sync.aligned.m8n8.x4.shared.b16 {%0,%1,%2,%3}, [%4];"
                 : "=r"(r[0]), "=r"(r[1]), "=r"(r[2]), "=r"(r[3]) : "r"(addr));
}

__device__ __forceinline__ void mma16816(float (&d)[4], const uint32_t (&a)[4],
                                         uint32_t b0, uint32_t b1) {
    asm volatile(
        "mma.sync.aligned.m16n8k16.row.col.f32.bf16.bf16.f32 "
        "{%0,%1,%2,%3}, {%4,%5,%6,%7}, {%8,%9}, {%0,%1,%2,%3};"
        : "+f"(d[0]), "+f"(d[1]), "+f"(d[2]), "+f"(d[3])
        : "r"(a[0]), "r"(a[1]), "r"(a[2]), "r"(a[3]), "r"(b0), "r"(b1));
}

__device__ __forceinline__ void split_bf16(float v, __nv_bfloat16& h, __nv_bfloat16& l) {
    h = __float2bfloat16(v);
    l = __float2bfloat16(v - __bfloat162float(h));
}

// ---------------------------------------------------------------------------
// PREP pass A (5120 blocks x 128 thr):
//   blocks [0,2048)    : gather items in (0, TH) -> fp32 partial acc + count
//   blocks [2048,4096) : codebook norms -> (cnorm, |c|)
//   blocks [4096,4608) : W1^T hi/lo split
//   blocks [4608,5120) : W2^T hi/lo split
// ---------------------------------------------------------------------------
__global__ void __launch_bounds__(128) prepA_kernel(
    const int* __restrict__ items, const float* __restrict__ item_embed,
    const float* __restrict__ codebook,
    const float* __restrict__ W1, const float* __restrict__ W2)
{
    __shared__ int   sidx[KHIST];
    __shared__ float ts[32][33];
    __shared__ float red[4];

    const int blk = blockIdx.x;
    const int t = threadIdx.x;

    if (blk < 2048) {
        int b = blk;
        for (int i = t; i < KHIST; i += 128) sidx[i] = items[b * KHIST + i];
        __syncthreads();
        const float4* E4 = (const float4*)item_embed;
        float4 acc = make_float4(0.f, 0.f, 0.f, 0.f);
        int cnt = 0;
        #pragma unroll 4
        for (int k = 0; k < KHIST; k++) {
            int idx = sidx[k];
            if (idx != 0 && idx < TH) {       // uniform across the block
                float4 v = E4[(size_t)idx * 128 + t];
                acc.x += v.x; acc.y += v.y; acc.z += v.z; acc.w += v.w;
                cnt++;
            }
        }
        ((float4*)g_macc)[(size_t)b * 128 + t] = acc;
        if (t == 0) g_mcnt[b] = cnt;
    } else if (blk < 4096) {
        int j = blk - 2048;
        float4 v = ((const float4*)codebook)[j * 128 + t];
        float s = v.x * v.x + v.y * v.y + v.z * v.z + v.w * v.w;
        #pragma unroll
        for (int o = 16; o > 0; o >>= 1) s += __shfl_down_sync(0xffffffffu, s, o);
        if ((t & 31) == 0) red[t >> 5] = s;
        __syncthreads();
        if (t == 0) {
            float cn = red[0] + red[1] + red[2] + red[3];
            g_cn2[j] = make_float2(cn, sqrtf(cn));
        }
    } else {
        const float* W;
        __nv_bfloat16 *WtH, *WtL;
        int KD, ND, w;
        if (blk < 4608) {
            w = blk - 4096; W = W1; WtH = g_W1tH; WtL = g_W1tL; KD = DD; ND = HHID;
        } else {
            w = blk - 4608; W = W2; WtH = g_W2tH; WtL = g_W2tL; KD = HHID; ND = DD;
        }
        int nblk = ND / 32;
        int n0 = (w % nblk) * 32, k0 = (w / nblk) * 32;
        int tx = t & 31, ty = t >> 5;
        #pragma unroll
        for (int i = ty; i < 32; i += 4)
            ts[i][tx] = W[(size_t)(k0 + i) * ND + n0 + tx];
        __syncthreads();
        #pragma unroll
        for (int i = ty; i < 32; i += 4) {
            float v = ts[tx][i];
            __nv_bfloat16 h, l;
            split_bf16(v, h, l);
            size_t o = (size_t)(n0 + i) * KD + k0 + tx;
            WtH[o] = h;
            WtL[o] = l;
        }
    }
}

// ---------------------------------------------------------------------------
// PREP pass B (2048 blocks x 128 thr): gather items >= TH, combine with
// pass-A partials, finalize mean, bf16 hi/lo split.
// ---------------------------------------------------------------------------
__global__ void __launch_bounds__(128) prepB_kernel(
    const int* __restrict__ items, const float* __restrict__ item_embed)
{
    __shared__ int sidx[KHIST];
    const int b = blockIdx.x;
    const int t = threadIdx.x;
    for (int i = t; i < KHIST; i += 128) sidx[i] = items[b * KHIST + i];
    __syncthreads();

    const float4* E4 = (const float4*)item_embed;
    float4 acc = ((const float4*)g_macc)[(size_t)b * 128 + t];
    int cnt = g_mcnt[b];
    #pragma unroll 4
    for (int k = 0; k < KHIST; k++) {
        int idx = sidx[k];
        if (idx >= TH) {                      // uniform across the block
            float4 v = E4[(size_t)idx * 128 + t];
            acc.x += v.x; acc.y += v.y; acc.z += v.z; acc.w += v.w;
            cnt++;
        }
    }
    float inv = 1.0f / (float)cnt;
    float vals[4] = {acc.x * inv, acc.y * inv, acc.z * inv, acc.w * inv};
    size_t base = (size_t)b * DD + t * 4;
    __nv_bfloat16 h[4], l[4];
    #pragma unroll
    for (int i = 0; i < 4; i++) split_bf16(vals[i], h[i], l[i]);
    *(__nv_bfloat162*)&g_meanH[base]     = {h[0], h[1]};
    *(__nv_bfloat162*)&g_meanH[base + 2] = {h[2], h[3]};
    *(__nv_bfloat162*)&g_meanL[base]     = {l[0], l[1]};
    *(__nv_bfloat162*)&g_meanL[base + 2] = {l[2], l[3]};
}

// ---------------------------------------------------------------------------
// Tensor-core GEMM (mma.sync bf16x3, fp32 accum): C = A[M,Kd] @ B[N,Kd]^T
// NS-stage cp.async pipeline (prefetch distance = NS chunks).
// WHICH=0: hid = relu(mean @ W1t^T + b1)  BM=128, NS=2, 2 CTAs/SM (compute-bound)
// WHICH=1: u   = hid @ W2t^T + b2         BM=128, NS=3, deep prefetch @1 CTA/SM
// ---------------------------------------------------------------------------
template<int BM, int WHICH, int NS>
__global__ void __launch_bounds__(256, (NS == 3) ? 1 : 2) gemm_mma(
    const __nv_bfloat16* __restrict__ Ah, const __nv_bfloat16* __restrict__ Al,
    const __nv_bfloat16* __restrict__ Bh, const __nv_bfloat16* __restrict__ Bl,
    const float* __restrict__ bias, float* __restrict__ out_ue,
    int N, int Kd)
{
    constexpr int BN  = 64;
    constexpr int WM  = BM / 4;
    constexpr int MT  = WM / 16;
    constexpr int STAGE = 2 * (BM + BN) * 128;

    extern __shared__ char smem[];
    const uint32_t sbase = smem_u32(smem);
    const int tid  = threadIdx.x;
    const int lane = tid & 31;
    const int w    = tid >> 5;
    const int warp_m0 = (w >> 1) * WM;
    const int warp_n0 = (w & 1) * 32;
    const int bm = blockIdx.y * BM, bn = blockIdx.x * BN;

    auto loadT = [&](const __nv_bfloat16* __restrict__ src, int row0, int k0,
                     uint32_t dst, int R) {
        #pragma unroll 4
        for (int i = 0; i < R * 8; i += 256) {
            int u = tid + i;
            int r = u >> 3, c8 = u & 7;
            uint32_t sd = dst + r * 128 + ((c8 * 16) ^ ((r & 7) << 4));
            const __nv_bfloat16* gs = src + (size_t)(row0 + r) * Kd + k0 + c8 * 8;
            CP_ASYNC16(sd, gs);
        }
    };
    auto issue = [&](int c, int buf) {
        uint32_t sb = sbase + (uint32_t)buf * STAGE;
        int k0 = c * 64;
        loadT(Ah, bm, k0, sb, BM);
        loadT(Al, bm, k0, sb + BM * 128, BM);
        loadT(Bh, bn, k0, sb + 2 * BM * 128, BN);
        loadT(Bl, bn, k0, sb + 2 * BM * 128 + BN * 128, BN);
    };

    const int tile = lane >> 3, lr = lane & 7;
    const uint32_t xorp = (uint32_t)(lr << 4);
    const int aRow = warp_m0 + ((tile & 1) << 3) + lr;
    const uint32_t aK = (uint32_t)((tile >> 1) << 4);
    const int bRow = warp_n0 + ((tile >> 1) << 3) + lr;
    const uint32_t bK = (uint32_t)((tile & 1) << 4);

    float acc[MT][4][4] = {};

    const int NC = Kd / 64;     // NC >= NS required (8 or 16 >= 2/3)

    // prologue: fill all NS buffers, then wait until chunk 0 is resident
    #pragma unroll
    for (int s = 0; s < NS; s++) { issue(s, s); CP_COMMIT(); }
    cp_wait<NS - 1>();
    __syncthreads();

    for (int c = 0; c < NC; c++) {
        uint32_t s0 = sbase + (uint32_t)(c % NS) * STAGE;
        uint32_t pA[2] = { s0, s0 + BM * 128 };
        uint32_t pB[2] = { s0 + 2 * BM * 128, s0 + 2 * BM * 128 + BN * 128 };

        #pragma unroll
        for (int kk = 0; kk < 4; kk++) {
            uint32_t akb = (((uint32_t)kk << 5) + aK) ^ xorp;
            uint32_t bkb = (((uint32_t)kk << 5) + bK) ^ xorp;
            uint32_t a[2][MT][4];
            uint32_t b[2][4][2];
            #pragma unroll
            for (int s = 0; s < 2; s++)
                #pragma unroll
                for (int mt = 0; mt < MT; mt++)
                    ldsm4(a[s][mt], pA[s] + (uint32_t)(aRow + mt * 16) * 128 + akb);
            #pragma unroll
            for (int s = 0; s < 2; s++)
                #pragma unroll
                for (int ng = 0; ng < 2; ng++) {
                    uint32_t t4[4];
                    ldsm4(t4, pB[s] + (uint32_t)(bRow + ng * 16) * 128 + bkb);
                    b[s][2 * ng][0] = t4[0]; b[s][2 * ng][1] = t4[1];
                    b[s][2 * ng + 1][0] = t4[2]; b[s][2 * ng + 1][1] = t4[3];
                }
            #pragma unroll
            for (int mt = 0; mt < MT; mt++)
                #pragma unroll
                for (int nt = 0; nt < 4; nt++)
                    mma16816(acc[mt][nt], a[0][mt], b[0][nt][0], b[0][nt][1]);
            #pragma unroll
            for (int mt = 0; mt < MT; mt++)
                #pragma unroll
                for (int nt = 0; nt < 4; nt++)
                    mma16816(acc[mt][nt], a[0][mt], b[1][nt][0], b[1][nt][1]);
            #pragma unroll
            for (int mt = 0; mt < MT; mt++)
                #pragma unroll
                for (int nt = 0; nt < 4; nt++)
                    mma16816(acc[mt][nt], a[1][mt], b[0][nt][0], b[0][nt][1]);
        }

        if (c == NC - 1) break;
        __syncthreads();                        // buffer c%NS now free
        int nx = c + NS;
        if (nx < NC) {
            issue(nx, c % NS); CP_COMMIT();
            cp_wait<NS - 1>();                  // chunk c+1 resident, NS-1 in flight
        } else {
            // no more issues; wait for chunk c+1 (pending = NC-c-2 groups)
            if (NS == 3 && c + 2 < NC) cp_wait<1>();
            else                       cp_wait<0>();
        }
        __syncthreads();
    }

    const int lr4 = lane >> 2;
    const int lc2 = (lane & 3) * 2;

    #pragma unroll
    for (int mt = 0; mt < MT; mt++)
        #pragma unroll
        for (int half = 0; half < 2; half++) {
            int row = bm + warp_m0 + mt * 16 + lr4 + half * 8;
            #pragma unroll
            for (int nt = 0; nt < 4; nt++) {
                int col = bn + warp_n0 + nt * 8 + lc2;
                float2 bv = *(const float2*)&bias[col];
                float v0 = acc[mt][nt][half * 2 + 0] + bv.x;
                float v1 = acc[mt][nt][half * 2 + 1] + bv.y;
                size_t o = (size_t)row * N + col;
                if (WHICH == 0) {
                    v0 = fmaxf(v0, 0.f); v1 = fmaxf(v1, 0.f);
                    __nv_bfloat16 h0, l0, h1, l1;
                    split_bf16(v0, h0, l0); split_bf16(v1, h1, l1);
                    *(__nv_bfloat162*)&g_hidH[o] = {h0, h1};
                    *(__nv_bfloat162*)&g_hidL[o] = {l0, l1};
                } else {
                    *(float2*)&g_u[o] = make_float2(v0, v1);
                    out_ue[o] = v0; out_ue[o + 1] = v1;
                }
            }
        }
}

// ---------------------------------------------------------------------------
// Fused VQ + epilogue (2048 blocks x 128 thr). Per batch row:
//   1. |u|; bound scan over packed (cnorm,|c|): keep j with
//      cnorm_j - 2|u||c_j| <= min_k(cnorm_k + 2|u||c_k|) + margin.
//      (Cauchy-Schwarz: true argmin always kept.)
//   2. exact fp32 dot per candidate; argmin, ties -> smaller j.
//   3. q/quant/pos/neg outputs + diff partial; last block reduces diff.
// ---------------------------------------------------------------------------
__global__ void __launch_bounds__(128) vq_epilogue_kernel(
    const float* __restrict__ codebook, const float* __restrict__ item_embed,
    const int* __restrict__ pos, const int* __restrict__ neg,
    float* __restrict__ out_q, float* __restrict__ out_pos,
    float* __restrict__ out_neg, float* __restrict__ out_diff)
{
    __shared__ float su[DD];          // u row (2 KB)
    __shared__ int   cand[CBK];       // candidate list (8 KB; worst case all)
    __shared__ float red[4];
    __shared__ float s_bcast;
    __shared__ int   s_cnt;
    __shared__ bool  s_last;

    const int b = blockIdx.x;
    const int t = threadIdx.x;

    // issue independent loads early (latency overlaps the scan below)
    const int pp = pos[b], nn = neg[b];
    const float4 pv4 = ((const float4*)item_embed)[(size_t)pp * 128 + t];
    const float4 nv4 = ((const float4*)item_embed)[(size_t)nn * 128 + t];

    // load u row; compute |u|
    float4 u4 = ((const float4*)g_u)[(size_t)b * 128 + t];
    ((float4*)su)[t] = u4;
    float p = u4.x * u4.x + u4.y * u4.y + u4.z * u4.z + u4.w * u4.w;
    #pragma unroll
    for (int o = 16; o > 0; o >>= 1) p += __shfl_down_sync(0xffffffffu, p, o);
    if ((t & 31) == 0) red[t >> 5] = p;
    if (t == 0) s_cnt = 0;
    __syncthreads();
    const float tu = 2.0f * sqrtf(red[0] + red[1] + red[2] + red[3]);

    // pass 1: U = min_j (cnorm_j + tu*|c_j|)
    float locU = 3.0e38f;
    for (int j = t; j < CBK; j += 128) {
        float2 c2 = g_cn2[j];
        locU = fminf(locU, fmaf(tu, c2.y, c2.x));
    }
    #pragma unroll
    for (int o = 16; o > 0; o >>= 1)
        locU = fminf(locU, __shfl_down_sync(0xffffffffu, locU, o));
    if ((t & 31) == 0) red[t >> 5] = locU;
    __syncthreads();
    const float U = fminf(fminf(red[0], red[1]), fminf(red[2], red[3])) + 1e-2f;

    // pass 2: collect candidates with lower bound <= U
    for (int j = t; j < CBK; j += 128) {
        float2 c2 = g_cn2[j];
        if (fmaf(-tu, c2.y, c2.x) <= U)
            cand[atomicAdd(&s_cnt, 1)] = j;
    }
    __syncthreads();
    const int ncand = s_cnt;

    // exact fp32 scores for candidates; argmin with smaller-j tie-break
    float best = 3.0e38f;
    int   bid  = 0x7fffffff;
    for (int i = 0; i < ncand; i++) {
        int j = cand[i];
        float4 c4 = ((const float4*)codebook)[(size_t)j * 128 + t];
        float4 uu = ((const float4*)su)[t];
        float d = c4.x * uu.x + c4.y * uu.y + c4.z * uu.z + c4.w * uu.w;
        #pragma unroll
        for (int o = 16; o > 0; o >>= 1) d += __shfl_down_sync(0xffffffffu, d, o);
        __syncthreads();               // protect red[] reuse
        if ((t & 31) == 0) red[t >> 5] = d;
        __syncthreads();
        if (t == 0) s_bcast = red[0] + red[1] + red[2] + red[3];
        __syncthreads();
        float s = g_cn2[j].x - 2.0f * s_bcast;
        if (s < best || (s == best && j < bid)) { best = s; bid = j; }
    }
    const int id = bid;

    // outputs
    float4 q = ((const float4*)codebook)[(size_t)id * 128 + t];
    float4 u = ((const float4*)su)[t];
    float4 d = make_float4(q.x - u.x, q.y - u.y, q.z - u.z, q.w - u.w);
    float4 qu = make_float4(u.x + d.x, u.y + d.y, u.z + d.z, u.w + d.w);
    ((float4*)out_q)[(size_t)b * 128 + t] = qu;
    ((float4*)out_pos)[(size_t)b * 128 + t] = pv4;
    ((float4*)out_neg)[(size_t)b * 128 + t] = nv4;

    float ds = d.x * d.x + d.y * d.y + d.z * d.z + d.w * d.w;
    #pragma unroll
    for (int o = 16; o > 0; o >>= 1) ds += __shfl_down_sync(0xffffffffu, ds, o);
    __syncthreads();
    if ((t & 31) == 0) red[t >> 5] = ds;
    __syncthreads();
    if (t == 0) {
        g_bsum[b] = red[0] + red[1] + red[2] + red[3];
        __threadfence();
        int c = atomicAdd(&g_count, 1);
        s_last = (c == BB - 1);
    }
    __syncthreads();

    if (s_last) {
        __threadfence();
        float s = 0.f;
        #pragma unroll
        for (int i = 0; i < BB / 128; i++) s += g_bsum[t + i * 128];
        __shared__ float sv[128];
        sv[t] = s;
        __syncthreads();
        for (int o = 64; o > 0; o >>= 1) {
            if (t < o) sv[t] += sv[t + o];
            __syncthreads();
        }
        if (t == 0) {
            *out_diff = sv[0] * (1.0f / (float)BD);
            g_count = 0;                       // reset for next graph replay
        }
    }
}

// ---------------------------------------------------------------------------
extern "C" void kernel_launch(void* const* d_in, const int* in_sizes, int n_in,
                              void* d_out, int out_size)
{
    const int*   items      = (const int*)  d_in[1];
    const int*   pos        = (const int*)  d_in[2];
    const int*   neg        = (const int*)  d_in[3];
    const float* item_embed = (const float*)d_in[4];
    const float* W1         = (const float*)d_in[5];
    const float* b1         = (const float*)d_in[6];
    const float* W2         = (const float*)d_in[7];
    const float* b2         = (const float*)d_in[8];
    const float* codebook   = (const float*)d_in[9];

    float* out      = (float*)d_out;
    float* out_q    = out;
    float* out_pos  = out + (size_t)BD;
    float* out_neg  = out + (size_t)2 * BD;
    float* out_diff = out + (size_t)3 * BD;
    float* out_ue   = out + (size_t)3 * BD + 1;

    const int SMEM_G0 = 2 * 2 * (128 + 64) * 128;  // 98304  (NS=2)
    const int SMEM_G1 = 3 * 2 * (128 + 64) * 128;  // 147456 (NS=3)
    cudaFuncSetAttribute((const void*)gemm_mma<128, 0, 2>,
                         cudaFuncAttributeMaxDynamicSharedMemorySize, SMEM_G0);
    cudaFuncSetAttribute((const void*)gemm_mma<128, 1, 3>,
                         cudaFuncAttributeMaxDynamicSharedMemorySize, SMEM_G1);

    __nv_bfloat16 *meanH, *meanL, *hidH, *hidL, *w1tH, *w1tL, *w2tH, *w2tL;
    cudaGetSymbolAddress((void**)&meanH, g_meanH);
    cudaGetSymbolAddress((void**)&meanL, g_meanL);
    cudaGetSymbolAddress((void**)&hidH,  g_hidH);
    cudaGetSymbolAddress((void**)&hidL,  g_hidL);
    cudaGetSymbolAddress((void**)&w1tH,  g_W1tH);
    cudaGetSymbolAddress((void**)&w1tL,  g_W1tL);
    cudaGetSymbolAddress((void**)&w2tH,  g_W2tH);
    cudaGetSymbolAddress((void**)&w2tL,  g_W2tL);

    // two-pass gather (L2-resident item ranges) + misc prep
    prepA_kernel<<<5120, 128>>>(items, item_embed, codebook, W1, W2);
    prepB_kernel<<<2048, 128>>>(items, item_embed);

    gemm_mma<128, 0, 2><<<dim3(HHID / 64, BB / 128), 256, SMEM_G0>>>(
        meanH, meanL, w1tH, w1tL, b1, nullptr, HHID, DD);
    gemm_mma<128, 1, 3><<<dim3(DD / 64, BB / 128), 256, SMEM_G1>>>(
        hidH,  hidL,  w2tH, w2tL, b2, out_ue,  DD,  HHID);

    vq_epilogue_kernel<<<BB, 128>>>(codebook, item_embed, pos, neg,
                                    out_q, out_pos, out_neg, out_diff);
}

// round 16
// speedup vs baseline: 1.7206x; 1.0067x over previous
#include <cuda_runtime.h>
#include <cuda_bf16.h>
#include <cstdint>

// Problem constants
#define BB    2048     // batch
#define KHIST 200      // history length
#define DD    512      // latent dim
#define HHID  1024     // 2*D
#define CBK   2048     // codebook size
#define BD    (BB*DD)  // 1048576
#define TH    50000    // item-id threshold: pass A < TH, pass B >= TH

// ---------------- scratch (device globals; no allocation allowed) ----------
__device__ float        g_part[2 * BB * DD];  // split-K partials for gemm1 (8 MB)
__device__ float2       g_cn2[CBK];           // (cnorm_j, |c_j|)
__device__ float        g_bsum[BB];
__device__ int          g_count;              // zero-init; self-resetting
__device__ float        g_macc[BB * DD];      // fp32 partial mean acc (pass A)
__device__ int          g_mcnt[BB];           // partial counts (pass A)

// bf16 hi/lo split operands
__device__ __nv_bfloat16 g_meanH[BB * DD],   g_meanL[BB * DD];
__device__ __nv_bfloat16 g_hidH [BB * HHID], g_hidL [BB * HHID];
__device__ __nv_bfloat16 g_W1tH [HHID * DD], g_W1tL [HHID * DD];
__device__ __nv_bfloat16 g_W2tH [DD * HHID], g_W2tL [DD * HHID];

// ---------------------------------------------------------------------------
// Portable PTX helpers (sm_80+; ptxas targets plain sm_103 — no tcgen05)
// ---------------------------------------------------------------------------
__device__ __forceinline__ uint32_t smem_u32(const void* p) {
    uint32_t a;
    asm("{ .reg .u64 t; cvta.to.shared.u64 t, %1; cvt.u32.u64 %0, t; }" : "=r"(a) : "l"(p));
    return a;
}

#define CP_ASYNC16(dst, src) \
    asm volatile("cp.async.cg.shared.global [%0], [%1], 16;" :: "r"(dst), "l"(src))
#define CP_COMMIT() asm volatile("cp.async.commit_group;" ::: "memory")
#define CP_WAIT0()  asm volatile("cp.async.wait_group 0;" ::: "memory")
#define CP_WAIT1()  asm volatile("cp.async.wait_group 1;" ::: "memory")

__device__ __forceinline__ void ldsm4(uint32_t (&r)[4], uint32_t addr) {
    asm volatile("ldmatrix.sync.aligned.m8n8.x4.shared.b16 {%0,%1,%2,%3}, [%4];"
                 : "=r"(r[0]), "=r"(r[1]), "=r"(r[2]), "=r"(r[3]) : "r"(addr));
}

__device__ __forceinline__ void mma16816(float (&d)[4], const uint32_t (&a)[4],
                                         uint32_t b0, uint32_t b1) {
    asm volatile(
        "mma.sync.aligned.m16n8k16.row.col.f32.bf16.bf16.f32 "
        "{%0,%1,%2,%3}, {%4,%5,%6,%7}, {%8,%9}, {%0,%1,%2,%3};"
        : "+f"(d[0]), "+f"(d[1]), "+f"(d[2]), "+f"(d[3])
        : "r"(a[0]), "r"(a[1]), "r"(a[2]), "r"(a[3]), "r"(b0), "r"(b1));
}

__device__ __forceinline__ void split_bf16(float v, __nv_bfloat16& h, __nv_bfloat16& l) {
    h = __float2bfloat16(v);
    l = __float2bfloat16(v - __bfloat162float(h));
}

// ---------------------------------------------------------------------------
// PREP pass A (5120 blocks x 128 thr):
//   blocks [0,2048)    : gather items in (0, TH) -> fp32 partial acc + count
//   blocks [2048,4096) : codebook norms -> (cnorm, |c|)
//   blocks [4096,4608) : W1^T hi/lo split
//   blocks [4608,5120) : W2^T hi/lo split
// ---------------------------------------------------------------------------
__global__ void __launch_bounds__(128) prepA_kernel(
    const int* __restrict__ items, const float* __restrict__ item_embed,
    const float* __restrict__ codebook,
    const float* __restrict__ W1, const float* __restrict__ W2)
{
    __shared__ int   sidx[KHIST];
    __shared__ float ts[32][33];
    __shared__ float red[4];

    const int blk = blockIdx.x;
    const int t = threadIdx.x;

    if (blk < 2048) {
        int b = blk;
        for (int i = t; i < KHIST; i += 128) sidx[i] = items[b * KHIST + i];
        __syncthreads();
        const float4* E4 = (const float4*)item_embed;
        float4 acc = make_float4(0.f, 0.f, 0.f, 0.f);
        int cnt = 0;
        #pragma unroll 4
        for (int k = 0; k < KHIST; k++) {
            int idx = sidx[k];
            if (idx != 0 && idx < TH) {       // uniform across the block
                float4 v = E4[(size_t)idx * 128 + t];
                acc.x += v.x; acc.y += v.y; acc.z += v.z; acc.w += v.w;
                cnt++;
            }
        }
        ((float4*)g_macc)[(size_t)b * 128 + t] = acc;
        if (t == 0) g_mcnt[b] = cnt;
    } else if (blk < 4096) {
        int j = blk - 2048;
        float4 v = ((const float4*)codebook)[j * 128 + t];
        float s = v.x * v.x + v.y * v.y + v.z * v.z + v.w * v.w;
        #pragma unroll
        for (int o = 16; o > 0; o >>= 1) s += __shfl_down_sync(0xffffffffu, s, o);
        if ((t & 31) == 0) red[t >> 5] = s;
        __syncthreads();
        if (t == 0) {
            float cn = red[0] + red[1] + red[2] + red[3];
            g_cn2[j] = make_float2(cn, sqrtf(cn));
        }
    } else {
        const float* W;
        __nv_bfloat16 *WtH, *WtL;
        int KD, ND, w;
        if (blk < 4608) {
            w = blk - 4096; W = W1; WtH = g_W1tH; WtL = g_W1tL; KD = DD; ND = HHID;
        } else {
            w = blk - 4608; W = W2; WtH = g_W2tH; WtL = g_W2tL; KD = HHID; ND = DD;
        }
        int nblk = ND / 32;
        int n0 = (w % nblk) * 32, k0 = (w / nblk) * 32;
        int tx = t & 31, ty = t >> 5;
        #pragma unroll
        for (int i = ty; i < 32; i += 4)
            ts[i][tx] = W[(size_t)(k0 + i) * ND + n0 + tx];
        __syncthreads();
        #pragma unroll
        for (int i = ty; i < 32; i += 4) {
            float v = ts[tx][i];
            __nv_bfloat16 h, l;
            split_bf16(v, h, l);
            size_t o = (size_t)(n0 + i) * KD + k0 + tx;
            WtH[o] = h;
            WtL[o] = l;
        }
    }
}

// ---------------------------------------------------------------------------
// PREP pass B (2048 blocks x 128 thr): gather items >= TH, combine with
// pass-A partials, finalize mean, bf16 hi/lo split.
// ---------------------------------------------------------------------------
__global__ void __launch_bounds__(128) prepB_kernel(
    const int* __restrict__ items, const float* __restrict__ item_embed)
{
    __shared__ int sidx[KHIST];
    const int b = blockIdx.x;
    const int t = threadIdx.x;
    for (int i = t; i < KHIST; i += 128) sidx[i] = items[b * KHIST + i];
    __syncthreads();

    const float4* E4 = (const float4*)item_embed;
    float4 acc = ((const float4*)g_macc)[(size_t)b * 128 + t];
    int cnt = g_mcnt[b];
    #pragma unroll 4
    for (int k = 0; k < KHIST; k++) {
        int idx = sidx[k];
        if (idx >= TH) {                      // uniform across the block
            float4 v = E4[(size_t)idx * 128 + t];
            acc.x += v.x; acc.y += v.y; acc.z += v.z; acc.w += v.w;
            cnt++;
        }
    }
    float inv = 1.0f / (float)cnt;
    float vals[4] = {acc.x * inv, acc.y * inv, acc.z * inv, acc.w * inv};
    size_t base = (size_t)b * DD + t * 4;
    __nv_bfloat16 h[4], l[4];
    #pragma unroll
    for (int i = 0; i < 4; i++) split_bf16(vals[i], h[i], l[i]);
    *(__nv_bfloat162*)&g_meanH[base]     = {h[0], h[1]};
    *(__nv_bfloat162*)&g_meanH[base + 2] = {h[2], h[3]};
    *(__nv_bfloat162*)&g_meanL[base]     = {l[0], l[1]};
    *(__nv_bfloat162*)&g_meanL[base + 2] = {l[2], l[3]};
}

// ---------------------------------------------------------------------------
// Tensor-core GEMM (mma.sync bf16x3, fp32 accum): C = A[M,*] @ B[N,*]^T over
// K range [blockIdx.z*Kd, (blockIdx.z+1)*Kd), row stride ldK. 2-stage cp.async.
// WHICH=0: hid = relu(mean @ W1t^T + b1) -> bf16 hi/lo   grid(16,16,1)
// WHICH=1: split-K partials of hid @ W2t^T -> g_part     grid(8,16,2)
// ---------------------------------------------------------------------------
template<int BM, int WHICH>
__global__ void __launch_bounds__(256, 2) gemm_mma(
    const __nv_bfloat16* __restrict__ Ah, const __nv_bfloat16* __restrict__ Al,
    const __nv_bfloat16* __restrict__ Bh, const __nv_bfloat16* __restrict__ Bl,
    const float* __restrict__ bias, float* __restrict__ pout,
    int N, int Kd, int ldK)
{
    constexpr int BN  = 64;
    constexpr int WM  = BM / 4;
    constexpr int MT  = WM / 16;
    constexpr int STAGE = 2 * (BM + BN) * 128;

    extern __shared__ char smem[];
    const uint32_t sbase = smem_u32(smem);
    const int tid  = threadIdx.x;
    const int lane = tid & 31;
    const int w    = tid >> 5;
    const int warp_m0 = (w >> 1) * WM;
    const int warp_n0 = (w & 1) * 32;
    const int bm = blockIdx.y * BM, bn = blockIdx.x * BN;
    const int kb = blockIdx.z * Kd;           // split-K base offset

    auto loadT = [&](const __nv_bfloat16* __restrict__ src, int row0, int k0,
                     uint32_t dst, int R) {
        #pragma unroll 4
        for (int i = 0; i < R * 8; i += 256) {
            int u = tid + i;
            int r = u >> 3, c8 = u & 7;
            uint32_t sd = dst + r * 128 + ((c8 * 16) ^ ((r & 7) << 4));
            const __nv_bfloat16* gs = src + (size_t)(row0 + r) * ldK + kb + k0 + c8 * 8;
            CP_ASYNC16(sd, gs);
        }
    };
    auto issue = [&](int c, int buf) {
        uint32_t sb = sbase + (uint32_t)buf * STAGE;
        int k0 = c * 64;
        loadT(Ah, bm, k0, sb, BM);
        loadT(Al, bm, k0, sb + BM * 128, BM);
        loadT(Bh, bn, k0, sb + 2 * BM * 128, BN);
        loadT(Bl, bn, k0, sb + 2 * BM * 128 + BN * 128, BN);
    };

    const int tile = lane >> 3, lr = lane & 7;
    const uint32_t xorp = (uint32_t)(lr << 4);
    const int aRow = warp_m0 + ((tile & 1) << 3) + lr;
    const uint32_t aK = (uint32_t)((tile >> 1) << 4);
    const int bRow = warp_n0 + ((tile >> 1) << 3) + lr;
    const uint32_t bK = (uint32_t)((tile & 1) << 4);

    float acc[MT][4][4] = {};

    const int NC = Kd / 64;
    issue(0, 0); CP_COMMIT();
    issue(1, 1); CP_COMMIT();
    CP_WAIT1();
    __syncthreads();

    for (int c = 0; c < NC; c++) {
        uint32_t s0 = sbase + (uint32_t)(c & 1) * STAGE;
        uint32_t pA[2] = { s0, s0 + BM * 128 };
        uint32_t pB[2] = { s0 + 2 * BM * 128, s0 + 2 * BM * 128 + BN * 128 };

        #pragma unroll
        for (int kk = 0; kk < 4; kk++) {
            uint32_t akb = (((uint32_t)kk << 5) + aK) ^ xorp;
            uint32_t bkb = (((uint32_t)kk << 5) + bK) ^ xorp;
            uint32_t a[2][MT][4];
            uint32_t b[2][4][2];
            #pragma unroll
            for (int s = 0; s < 2; s++)
                #pragma unroll
                for (int mt = 0; mt < MT; mt++)
                    ldsm4(a[s][mt], pA[s] + (uint32_t)(aRow + mt * 16) * 128 + akb);
            #pragma unroll
            for (int s = 0; s < 2; s++)
                #pragma unroll
                for (int ng = 0; ng < 2; ng++) {
                    uint32_t t4[4];
                    ldsm4(t4, pB[s] + (uint32_t)(bRow + ng * 16) * 128 + bkb);
                    b[s][2 * ng][0] = t4[0]; b[s][2 * ng][1] = t4[1];
                    b[s][2 * ng + 1][0] = t4[2]; b[s][2 * ng + 1][1] = t4[3];
                }
            #pragma unroll
            for (int mt = 0; mt < MT; mt++)
                #pragma unroll
                for (int nt = 0; nt < 4; nt++)
                    mma16816(acc[mt][nt], a[0][mt], b[0][nt][0], b[0][nt][1]);
            #pragma unroll
            for (int mt = 0; mt < MT; mt++)
                #pragma unroll
                for (int nt = 0; nt < 4; nt++)
                    mma16816(acc[mt][nt], a[0][mt], b[1][nt][0], b[1][nt][1]);
            #pragma unroll
            for (int mt = 0; mt < MT; mt++)
                #pragma unroll
                for (int nt = 0; nt < 4; nt++)
                    mma16816(acc[mt][nt], a[1][mt], b[0][nt][0], b[0][nt][1]);
        }

        if (c == NC - 1) break;
        __syncthreads();
        if (c + 2 < NC) { issue(c + 2, c & 1); CP_COMMIT(); CP_WAIT1(); }
        else            { CP_WAIT0(); }
        __syncthreads();
    }

    const int lr4 = lane >> 2;
    const int lc2 = (lane & 3) * 2;

    #pragma unroll
    for (int mt = 0; mt < MT; mt++)
        #pragma unroll
        for (int half = 0; half < 2; half++) {
            int row = bm + warp_m0 + mt * 16 + lr4 + half * 8;
            #pragma unroll
            for (int nt = 0; nt < 4; nt++) {
                int col = bn + warp_n0 + nt * 8 + lc2;
                float v0 = acc[mt][nt][half * 2 + 0];
                float v1 = acc[mt][nt][half * 2 + 1];
                if (WHICH == 0) {
                    float2 bv = *(const float2*)&bias[col];
                    v0 = fmaxf(v0 + bv.x, 0.f);
                    v1 = fmaxf(v1 + bv.y, 0.f);
                    size_t o = (size_t)row * N + col;
                    __nv_bfloat16 h0, l0, h1, l1;
                    split_bf16(v0, h0, l0); split_bf16(v1, h1, l1);
                    *(__nv_bfloat162*)&g_hidH[o] = {h0, h1};
                    *(__nv_bfloat162*)&g_hidL[o] = {l0, l1};
                } else {
                    // raw split-K partial (bias added in VQ kernel)
                    size_t o = (size_t)blockIdx.z * BD + (size_t)row * N + col;
                    *(float2*)&pout[o] = make_float2(v0, v1);
                }
            }
        }
}

// ---------------------------------------------------------------------------
// Fused split-K combine + VQ + epilogue (2048 blocks x 128 thr). Per row:
//   0. u = part0 + part1 + b2 (fp32); write out_ue (scalar, misaligned base).
//   1. |u|; bound scan over packed (cnorm,|c|): keep j with
//      cnorm_j - 2|u||c_j| <= min_k(cnorm_k + 2|u||c_k|) + margin.
//      (Cauchy-Schwarz: true argmin always kept.)
//   2. exact fp32 dot per candidate; argmin, ties -> smaller j.
//   3. q/quant/pos/neg outputs + diff partial; last block reduces diff.
// ---------------------------------------------------------------------------
__global__ void __launch_bounds__(128) vq_epilogue_kernel(
    const float* __restrict__ codebook, const float* __restrict__ item_embed,
    const int* __restrict__ pos, const int* __restrict__ neg,
    const float* __restrict__ b2,
    float* __restrict__ out_q, float* __restrict__ out_pos,
    float* __restrict__ out_neg, float* __restrict__ out_diff,
    float* __restrict__ out_ue)
{
    __shared__ float su[DD];          // u row (2 KB)
    __shared__ int   cand[CBK];       // candidate list (8 KB; worst case all)
    __shared__ float red[4];
    __shared__ float s_bcast;
    __shared__ int   s_cnt;
    __shared__ bool  s_last;

    const int b = blockIdx.x;
    const int t = threadIdx.x;

    // issue independent loads early (latency overlaps the work below)
    const int pp = pos[b], nn = neg[b];
    const float4 pv4 = ((const float4*)item_embed)[(size_t)pp * 128 + t];
    const float4 nv4 = ((const float4*)item_embed)[(size_t)nn * 128 + t];

    // split-K combine: u = p0 + p1 + bias
    float4 p0 = ((const float4*)g_part)[(size_t)b * 128 + t];
    float4 p1 = ((const float4*)(g_part + BD))[(size_t)b * 128 + t];
    float4 bb = ((const float4*)b2)[t];
    float4 u4 = make_float4(p0.x + p1.x + bb.x, p0.y + p1.y + bb.y,
                            p0.z + p1.z + bb.z, p0.w + p1.w + bb.w);
    ((float4*)su)[t] = u4;
    {   // user_embed output (destination only 4B-aligned)
        size_t o = (size_t)b * DD + t * 4;
        out_ue[o + 0] = u4.x; out_ue[o + 1] = u4.y;
        out_ue[o + 2] = u4.z; out_ue[o + 3] = u4.w;
    }

    float p = u4.x * u4.x + u4.y * u4.y + u4.z * u4.z + u4.w * u4.w;
    #pragma unroll
    for (int o = 16; o > 0; o >>= 1) p += __shfl_down_sync(0xffffffffu, p, o);
    if ((t & 31) == 0) red[t >> 5] = p;
    if (t == 0) s_cnt = 0;
    __syncthreads();
    const float tu = 2.0f * sqrtf(red[0] + red[1] + red[2] + red[3]);

    // pass 1: U = min_j (cnorm_j + tu*|c_j|)
    float locU = 3.0e38f;
    for (int j = t; j < CBK; j += 128) {
        float2 c2 = g_cn2[j];
        locU = fminf(locU, fmaf(tu, c2.y, c2.x));
    }
    #pragma unroll
    for (int o = 16; o > 0; o >>= 1)
        locU = fminf(locU, __shfl_down_sync(0xffffffffu, locU, o));
    if ((t & 31) == 0) red[t >> 5] = locU;
    __syncthreads();
    const float U = fminf(fminf(red[0], red[1]), fminf(red[2], red[3])) + 1e-2f;

    // pass 2: collect candidates with lower bound <= U
    for (int j = t; j < CBK; j += 128) {
        float2 c2 = g_cn2[j];
        if (fmaf(-tu, c2.y, c2.x) <= U)
            cand[atomicAdd(&s_cnt, 1)] = j;
    }
    __syncthreads();
    const int ncand = s_cnt;

    // exact fp32 scores for candidates; argmin with smaller-j tie-break
    float best = 3.0e38f;
    int   bid  = 0x7fffffff;
    for (int i = 0; i < ncand; i++) {
        int j = cand[i];
        float4 c4 = ((const float4*)codebook)[(size_t)j * 128 + t];
        float4 uu = ((const float4*)su)[t];
        float d = c4.x * uu.x + c4.y * uu.y + c4.z * uu.z + c4.w * uu.w;
        #pragma unroll
        for (int o = 16; o > 0; o >>= 1) d += __shfl_down_sync(0xffffffffu, d, o);
        __syncthreads();               // protect red[] reuse
        if ((t & 31) == 0) red[t >> 5] = d;
        __syncthreads();
        if (t == 0) s_bcast = red[0] + red[1] + red[2] + red[3];
        __syncthreads();
        float s = g_cn2[j].x - 2.0f * s_bcast;
        if (s < best || (s == best && j < bid)) { best = s; bid = j; }
    }
    const int id = bid;

    // outputs
    float4 q = ((const float4*)codebook)[(size_t)id * 128 + t];
    float4 u = ((const float4*)su)[t];
    float4 d = make_float4(q.x - u.x, q.y - u.y, q.z - u.z, q.w - u.w);
    float4 qu = make_float4(u.x + d.x, u.y + d.y, u.z + d.z, u.w + d.w);
    ((float4*)out_q)[(size_t)b * 128 + t] = qu;
    ((float4*)out_pos)[(size_t)b * 128 + t] = pv4;
    ((float4*)out_neg)[(size_t)b * 128 + t] = nv4;

    float ds = d.x * d.x + d.y * d.y + d.z * d.z + d.w * d.w;
    #pragma unroll
    for (int o = 16; o > 0; o >>= 1) ds += __shfl_down_sync(0xffffffffu, ds, o);
    __syncthreads();
    if ((t & 31) == 0) red[t >> 5] = ds;
    __syncthreads();
    if (t == 0) {
        g_bsum[b] = red[0] + red[1] + red[2] + red[3];
        __threadfence();
        int c = atomicAdd(&g_count, 1);
        s_last = (c == BB - 1);
    }
    __syncthreads();

    if (s_last) {
        __threadfence();
        float s = 0.f;
        #pragma unroll
        for (int i = 0; i < BB / 128; i++) s += g_bsum[t + i * 128];
        __shared__ float sv[128];
        sv[t] = s;
        __syncthreads();
        for (int o = 64; o > 0; o >>= 1) {
            if (t < o) sv[t] += sv[t + o];
            __syncthreads();
        }
        if (t == 0) {
            *out_diff = sv[0] * (1.0f / (float)BD);
            g_count = 0;                       // reset for next graph replay
        }
    }
}

// ---------------------------------------------------------------------------
extern "C" void kernel_launch(void* const* d_in, const int* in_sizes, int n_in,
                              void* d_out, int out_size)
{
    const int*   items      = (const int*)  d_in[1];
    const int*   pos        = (const int*)  d_in[2];
    const int*   neg        = (const int*)  d_in[3];
    const float* item_embed = (const float*)d_in[4];
    const float* W1         = (const float*)d_in[5];
    const float* b1         = (const float*)d_in[6];
    const float* W2         = (const float*)d_in[7];
    const float* b2         = (const float*)d_in[8];
    const float* codebook   = (const float*)d_in[9];

    float* out      = (float*)d_out;
    float* out_q    = out;
    float* out_pos  = out + (size_t)BD;
    float* out_neg  = out + (size_t)2 * BD;
    float* out_diff = out + (size_t)3 * BD;
    float* out_ue   = out + (size_t)3 * BD + 1;

    const int SMEM_G = 2 * 2 * (128 + 64) * 128;   // 98304 (2 stages)
    cudaFuncSetAttribute((const void*)gemm_mma<128, 0>,
                         cudaFuncAttributeMaxDynamicSharedMemorySize, SMEM_G);
    cudaFuncSetAttribute((const void*)gemm_mma<128, 1>,
                         cudaFuncAttributeMaxDynamicSharedMemorySize, SMEM_G);

    __nv_bfloat16 *meanH, *meanL, *hidH, *hidL, *w1tH, *w1tL, *w2tH, *w2tL;
    float* partp;
    cudaGetSymbolAddress((void**)&meanH, g_meanH);
    cudaGetSymbolAddress((void**)&meanL, g_meanL);
    cudaGetSymbolAddress((void**)&hidH,  g_hidH);
    cudaGetSymbolAddress((void**)&hidL,  g_hidL);
    cudaGetSymbolAddress((void**)&w1tH,  g_W1tH);
    cudaGetSymbolAddress((void**)&w1tL,  g_W1tL);
    cudaGetSymbolAddress((void**)&w2tH,  g_W2tH);
    cudaGetSymbolAddress((void**)&w2tL,  g_W2tL);
    cudaGetSymbolAddress((void**)&partp, g_part);

    // two-pass gather (L2-resident item ranges) + misc prep
    prepA_kernel<<<5120, 128>>>(items, item_embed, codebook, W1, W2);
    prepB_kernel<<<2048, 128>>>(items, item_embed);

    // gemm0: full-K, grid 256 -> 2 CTAs/SM, compute-bound
    gemm_mma<128, 0><<<dim3(HHID / 64, BB / 128, 1), 256, SMEM_G>>>(
        meanH, meanL, w1tH, w1tL, b1, nullptr, HHID, DD, DD);
    // gemm1: split-K (z=2 halves of K=1024), grid 256 -> 2 CTAs/SM
    gemm_mma<128, 1><<<dim3(DD / 64, BB / 128, 2), 256, SMEM_G>>>(
        hidH, hidL, w2tH, w2tL, nullptr, partp, DD, HHID / 2, HHID);

    vq_epilogue_kernel<<<BB, 128>>>(codebook, item_embed, pos, neg, b2,
                                    out_q, out_pos, out_neg, out_diff, out_ue);
}